// round 2
// baseline (speedup 1.0000x reference)
#include <cuda_runtime.h>
#include <math.h>

// Problem dims (fixed)
constexpr int BATCH = 4;
constexpr int TLEN  = 2048;
constexpr int HD    = 2048;
constexpr int MROWS = BATCH * TLEN;          // 8192
constexpr size_t TOT = (size_t)MROWS * HD;   // 16,777,216

// Scratch (device globals: allocation-free per harness rules)
__device__ float g_mk[TOT];   // key mix, later reused as p = r * rwkv
__device__ float g_mv[TOT];   // value mix
__device__ float g_mr[TOT];   // receptance mix
__device__ float g_k[TOT];
__device__ float g_v[TOT];
__device__ float g_r[TOT];

// ---------------------------------------------------------------------------
// Elementwise time-shift + three mixes (float4 vectorized)
// ---------------------------------------------------------------------------
__global__ void mix_kernel(const float* __restrict__ hidden,
                           const float* __restrict__ tmk,
                           const float* __restrict__ tmv,
                           const float* __restrict__ tmr) {
    int idx = blockIdx.x * blockDim.x + threadIdx.x;      // float4 index
    constexpr int HV = HD / 4;
    int row = idx / HV;          // global row over B*T
    int hv  = idx % HV;
    bool hasPrev = (row % TLEN) != 0;

    const float4* h4 = (const float4*)hidden;
    float4 cur  = h4[idx];
    float4 prev = hasPrev ? h4[idx - HV] : make_float4(0.f, 0.f, 0.f, 0.f);

    float4 mk = ((const float4*)tmk)[hv];
    float4 mv = ((const float4*)tmv)[hv];
    float4 mr = ((const float4*)tmr)[hv];

    // cur*m + prev*(1-m) == prev + m*(cur-prev)
    float4 dk, dv, dr;
    dk.x = prev.x + mk.x * (cur.x - prev.x);
    dk.y = prev.y + mk.y * (cur.y - prev.y);
    dk.z = prev.z + mk.z * (cur.z - prev.z);
    dk.w = prev.w + mk.w * (cur.w - prev.w);
    dv.x = prev.x + mv.x * (cur.x - prev.x);
    dv.y = prev.y + mv.y * (cur.y - prev.y);
    dv.z = prev.z + mv.z * (cur.z - prev.z);
    dv.w = prev.w + mv.w * (cur.w - prev.w);
    dr.x = prev.x + mr.x * (cur.x - prev.x);
    dr.y = prev.y + mr.y * (cur.y - prev.y);
    dr.z = prev.z + mr.z * (cur.z - prev.z);
    dr.w = prev.w + mr.w * (cur.w - prev.w);

    ((float4*)g_mk)[idx] = dk;
    ((float4*)g_mv)[idx] = dv;
    ((float4*)g_mr)[idx] = dr;
}

// ---------------------------------------------------------------------------
// Tiled fp32 SGEMM: C[M,N] = A[M,K] @ B[K,N]
// M=8192, N=K=2048 hardcoded.  128x128 block tile, BK=8, 256 threads, 8x8 micro.
// EPI: 0 = none, 1 = sigmoid
// ---------------------------------------------------------------------------
template <int EPI>
__global__ __launch_bounds__(256, 2)
void sgemm128(const float* __restrict__ A,
              const float* __restrict__ Bm,
              float* __restrict__ C) {
    constexpr int M = MROWS, N = HD, K = HD;
    constexpr int BM = 128, BN = 128, BK = 8;

    __shared__ float As[BK][BM];
    __shared__ float Bs[BK][BN];

    int tid = threadIdx.x;
    int ty = tid >> 4;          // 0..15
    int tx = tid & 15;          // 0..15
    int mBase = blockIdx.y * BM;
    int nBase = blockIdx.x * BN;

    // A tile load mapping: 128 rows x 8 cols, 2 float4 per row
    int aRow = tid >> 1;            // 0..127
    int aSeg = (tid & 1) * 4;       // 0 or 4
    // B tile load mapping: 8 rows x 128 cols, 32 float4 per row
    int bRow = tid >> 5;            // 0..7
    int bCol = (tid & 31) * 4;      // 0..124

    const float* Aptr = A + (size_t)(mBase + aRow) * K + aSeg;
    const float* Bptr = Bm + (size_t)bRow * N + nBase + bCol;

    float acc[8][8];
    #pragma unroll
    for (int i = 0; i < 8; i++)
        #pragma unroll
        for (int j = 0; j < 8; j++) acc[i][j] = 0.f;

    for (int k0 = 0; k0 < K; k0 += BK) {
        float4 av = *(const float4*)(Aptr + k0);
        float4 bv = *(const float4*)(Bptr + (size_t)k0 * N);
        As[aSeg + 0][aRow] = av.x;
        As[aSeg + 1][aRow] = av.y;
        As[aSeg + 2][aRow] = av.z;
        As[aSeg + 3][aRow] = av.w;
        *(float4*)&Bs[bRow][bCol] = bv;
        __syncthreads();

        #pragma unroll
        for (int kk = 0; kk < BK; kk++) {
            float a[8], b[8];
            *(float4*)(a)     = *(const float4*)&As[kk][ty * 8];
            *(float4*)(a + 4) = *(const float4*)&As[kk][ty * 8 + 4];
            *(float4*)(b)     = *(const float4*)&Bs[kk][tx * 8];
            *(float4*)(b + 4) = *(const float4*)&Bs[kk][tx * 8 + 4];
            #pragma unroll
            for (int i = 0; i < 8; i++)
                #pragma unroll
                for (int j = 0; j < 8; j++)
                    acc[i][j] = fmaf(a[i], b[j], acc[i][j]);
        }
        __syncthreads();
    }

    #pragma unroll
    for (int i = 0; i < 8; i++) {
        float* Crow = C + (size_t)(mBase + ty * 8 + i) * N + nBase + tx * 8;
        #pragma unroll
        for (int jj = 0; jj < 2; jj++) {
            float4 o;
            o.x = acc[i][jj * 4 + 0];
            o.y = acc[i][jj * 4 + 1];
            o.z = acc[i][jj * 4 + 2];
            o.w = acc[i][jj * 4 + 3];
            if (EPI == 1) {
                o.x = 1.f / (1.f + __expf(-o.x));
                o.y = 1.f / (1.f + __expf(-o.y));
                o.z = 1.f / (1.f + __expf(-o.z));
                o.w = 1.f / (1.f + __expf(-o.w));
            }
            *(float4*)(Crow + jj * 4) = o;
        }
    }
}

// ---------------------------------------------------------------------------
// WKV scan: one thread per (b, d) channel. Fuses the final r* multiply,
// writing p = r * rwkv into g_mk (reused).
// ---------------------------------------------------------------------------
__global__ void wkv_kernel(const float* __restrict__ time_decay,
                           const float* __restrict__ time_first) {
    int idx = blockIdx.x * blockDim.x + threadIdx.x;   // 0..8191
    int b = idx / HD;
    int d = idx % HD;

    float td = -__expf(time_decay[d]);
    float tf = time_first[d];

    float num = 0.f, den = 0.f, mx = -1e38f;
    size_t base = (size_t)b * TLEN * HD + d;

    float kt = g_k[base];
    float vt = g_v[base];

    for (int t = 0; t < TLEN; t++) {
        size_t off = base + (size_t)t * HD;
        float ktn = 0.f, vtn = 0.f;
        if (t + 1 < TLEN) {
            ktn = g_k[off + HD];
            vtn = g_v[off + HD];
        }
        float rt = g_r[off];

        // output from current state
        float mfo = fmaxf(mx, kt + tf);
        float e1  = __expf(mx - mfo);
        float e2  = __expf(kt + tf - mfo);
        float out = (e1 * num + e2 * vt) / (e1 * den + e2);

        // state update with decay
        float mfs = fmaxf(mx + td, kt);
        float e1s = __expf(mx + td - mfs);
        float e2s = __expf(kt - mfs);
        num = e1s * num + e2s * vt;
        den = e1s * den + e2s;
        mx  = mfs;

        g_mk[off] = out * rt;

        kt = ktn;
        vt = vtn;
    }
}

// ---------------------------------------------------------------------------
// Launch
// ---------------------------------------------------------------------------
extern "C" void kernel_launch(void* const* d_in, const int* in_sizes, int n_in,
                              void* d_out, int out_size) {
    const float* hidden = (const float*)d_in[0];
    const float* time_decay = (const float*)d_in[1];
    const float* time_first = (const float*)d_in[2];
    const float* tmk = (const float*)d_in[3];
    const float* tmv = (const float*)d_in[4];
    const float* tmr = (const float*)d_in[5];
    const float* Wk = (const float*)d_in[6];
    const float* Wv = (const float*)d_in[7];
    const float* Wr = (const float*)d_in[8];
    const float* Wo = (const float*)d_in[9];

    float *mk, *mv, *mr, *kb, *vb, *rb;
    cudaGetSymbolAddress((void**)&mk, g_mk);
    cudaGetSymbolAddress((void**)&mv, g_mv);
    cudaGetSymbolAddress((void**)&mr, g_mr);
    cudaGetSymbolAddress((void**)&kb, g_k);
    cudaGetSymbolAddress((void**)&vb, g_v);
    cudaGetSymbolAddress((void**)&rb, g_r);

    // 1. mixes
    mix_kernel<<<(int)(TOT / 4 / 256), 256>>>(hidden, tmk, tmv, tmr);

    // 2. three input GEMMs
    dim3 grid(HD / 128, MROWS / 128);
    sgemm128<0><<<grid, 256>>>(mk, Wk, kb);
    sgemm128<0><<<grid, 256>>>(mv, Wv, vb);
    sgemm128<1><<<grid, 256>>>(mr, Wr, rb);

    // 3. WKV scan (fused r*), writes p into g_mk
    wkv_kernel<<<MROWS / 256, 256>>>(time_decay, time_first);

    // 4. output GEMM
    sgemm128<0><<<grid, 256>>>(mk, Wo, (float*)d_out);
}

// round 4
// speedup vs baseline: 2.0141x; 2.0141x over previous
#include <cuda_runtime.h>
#include <cuda_bf16.h>
#include <cstdint>
#include <math.h>

// ---------------------------------------------------------------------------
// Problem dims (fixed)
// ---------------------------------------------------------------------------
constexpr int BATCH = 4;
constexpr int TLEN  = 2048;
constexpr int HD    = 2048;                  // N = K = 2048
constexpr int MROWS = BATCH * TLEN;          // 8192
constexpr size_t TOT = (size_t)MROWS * HD;   // 16,777,216

// GEMM tiling
constexpr int BM = 128;
constexpr int BN = 128;
constexpr int BK = 32;
constexpr int NITER = HD / BK;               // 64
constexpr int STAGES = 3;
constexpr int PITCH = 80;                    // bytes per 32-bf16 row (64 data + 16 pad)
constexpr int PLANE = 128 * PITCH;           // 10240 bytes per plane tile
constexpr int STAGE_BYTES = 4 * PLANE;       // Ah, Al, Bh, Bl = 40960
constexpr int SMEM_GEMM = STAGES * STAGE_BYTES;  // 122880

// ---------------------------------------------------------------------------
// Scratch (device globals: allocation-free per harness rules)
// ---------------------------------------------------------------------------
__device__ __align__(256) __nv_bfloat16 g_akh[TOT];  // key-mix hi (reused for p hi)
__device__ __align__(256) __nv_bfloat16 g_akl[TOT];  // key-mix lo (reused for p lo)
__device__ __align__(256) __nv_bfloat16 g_avh[TOT];
__device__ __align__(256) __nv_bfloat16 g_avl[TOT];
__device__ __align__(256) __nv_bfloat16 g_arh[TOT];
__device__ __align__(256) __nv_bfloat16 g_arl[TOT];
__device__ __align__(256) float g_k[TOT];
__device__ __align__(256) float g_v[TOT];
__device__ __align__(256) float g_r[TOT];
// transposed+split weights: [N=2048, K=2048] bf16, K-major
__device__ __align__(256) __nv_bfloat16 g_wkh[HD * HD];
__device__ __align__(256) __nv_bfloat16 g_wkl[HD * HD];
__device__ __align__(256) __nv_bfloat16 g_wvh[HD * HD];
__device__ __align__(256) __nv_bfloat16 g_wvl[HD * HD];
__device__ __align__(256) __nv_bfloat16 g_wrh[HD * HD];
__device__ __align__(256) __nv_bfloat16 g_wrl[HD * HD];
__device__ __align__(256) __nv_bfloat16 g_woh[HD * HD];
__device__ __align__(256) __nv_bfloat16 g_wol[HD * HD];

// ---------------------------------------------------------------------------
// PTX helpers (base sm_103 target only: cp.async, ldmatrix, mma.sync)
// ---------------------------------------------------------------------------
__device__ __forceinline__ uint32_t smem_u32(const void* p) {
    uint32_t a;
    asm("{ .reg .u64 t; cvta.to.shared.u64 t, %1; cvt.u32.u64 %0, t; }"
        : "=r"(a) : "l"(p));
    return a;
}

__device__ __forceinline__ void cp_async16(uint32_t s, const void* g) {
    asm volatile("cp.async.cg.shared.global [%0], [%1], 16;" :: "r"(s), "l"(g));
}
__device__ __forceinline__ void cp_commit() {
    asm volatile("cp.async.commit_group;" ::: "memory");
}
template <int N>
__device__ __forceinline__ void cp_wait() {
    asm volatile("cp.async.wait_group %0;" :: "n"(N) : "memory");
}

__device__ __forceinline__ void ldsm_x4(uint32_t* r, uint32_t addr) {
    asm volatile("ldmatrix.sync.aligned.m8n8.x4.shared.b16 {%0,%1,%2,%3}, [%4];"
        : "=r"(r[0]), "=r"(r[1]), "=r"(r[2]), "=r"(r[3]) : "r"(addr));
}

__device__ __forceinline__ uint32_t lds32(uint32_t addr) {
    uint32_t v;
    asm volatile("ld.shared.b32 %0, [%1];" : "=r"(v) : "r"(addr));
    return v;
}

// mma.sync m16n8k16 bf16 -> fp32, D += A*B
__device__ __forceinline__ void mma16816(float* d, const uint32_t* a, const uint32_t* b) {
    asm volatile(
        "mma.sync.aligned.m16n8k16.row.col.f32.bf16.bf16.f32 "
        "{%0,%1,%2,%3}, {%4,%5,%6,%7}, {%8,%9}, {%0,%1,%2,%3};"
        : "+f"(d[0]), "+f"(d[1]), "+f"(d[2]), "+f"(d[3])
        : "r"(a[0]), "r"(a[1]), "r"(a[2]), "r"(a[3]), "r"(b[0]), "r"(b[1]));
}

// ---------------------------------------------------------------------------
// bf16 split helpers
// ---------------------------------------------------------------------------
__device__ __forceinline__ void split_bf16(float v, __nv_bfloat16& h, __nv_bfloat16& l) {
    h = __float2bfloat16(v);
    l = __float2bfloat16(v - __bfloat162float(h));
}
__device__ __forceinline__ uint32_t pack2(__nv_bfloat16 a, __nv_bfloat16 b) {
    __nv_bfloat162 t(a, b);
    return *(uint32_t*)&t;
}

// ---------------------------------------------------------------------------
// Weight transpose + hi/lo split:  W[K,N] fp32 -> Th[N,K], Tl[N,K] bf16
// ---------------------------------------------------------------------------
__global__ void transpose_split(const float* __restrict__ W,
                                __nv_bfloat16* __restrict__ Th,
                                __nv_bfloat16* __restrict__ Tl) {
    __shared__ float tile[32][33];
    int tx = threadIdx.x & 31;
    int ty0 = threadIdx.x >> 5;          // 0..7
    int bx = blockIdx.x * 32;            // n base
    int by = blockIdx.y * 32;            // k base
    #pragma unroll
    for (int i = 0; i < 32; i += 8)
        tile[ty0 + i][tx] = W[(size_t)(by + ty0 + i) * HD + bx + tx];
    __syncthreads();
    #pragma unroll
    for (int i = 0; i < 32; i += 8) {
        float v = tile[tx][ty0 + i];
        __nv_bfloat16 h, l;
        split_bf16(v, h, l);
        size_t o = (size_t)(bx + ty0 + i) * HD + by + tx;
        Th[o] = h;
        Tl[o] = l;
    }
}

// ---------------------------------------------------------------------------
// Time-shift + three mixes -> six bf16 planes (hi/lo for k, v, r)
// ---------------------------------------------------------------------------
__global__ void mix_kernel(const float* __restrict__ hidden,
                           const float* __restrict__ tmk,
                           const float* __restrict__ tmv,
                           const float* __restrict__ tmr) {
    int idx = blockIdx.x * blockDim.x + threadIdx.x;  // float4 index
    constexpr int HV = HD / 4;
    int row = idx / HV;
    int hv  = idx % HV;
    bool hasPrev = (row % TLEN) != 0;

    const float4* h4 = (const float4*)hidden;
    float4 cur  = h4[idx];
    float4 prev = hasPrev ? h4[idx - HV] : make_float4(0.f, 0.f, 0.f, 0.f);

    float4 mk = ((const float4*)tmk)[hv];
    float4 mv = ((const float4*)tmv)[hv];
    float4 mr = ((const float4*)tmr)[hv];

    float c[4] = {cur.x, cur.y, cur.z, cur.w};
    float p[4] = {prev.x, prev.y, prev.z, prev.w};
    float k_[4] = {mk.x, mk.y, mk.z, mk.w};
    float v_[4] = {mv.x, mv.y, mv.z, mv.w};
    float r_[4] = {mr.x, mr.y, mr.z, mr.w};
    float dk[4], dv[4], dr[4];
    #pragma unroll
    for (int i = 0; i < 4; i++) {
        dk[i] = p[i] + k_[i] * (c[i] - p[i]);
        dv[i] = p[i] + v_[i] * (c[i] - p[i]);
        dr[i] = p[i] + r_[i] * (c[i] - p[i]);
    }

    __nv_bfloat16 h[4], l[4];
    uint2 out;
    #pragma unroll
    for (int i = 0; i < 4; i++) split_bf16(dk[i], h[i], l[i]);
    out.x = pack2(h[0], h[1]); out.y = pack2(h[2], h[3]);
    ((uint2*)g_akh)[idx] = out;
    out.x = pack2(l[0], l[1]); out.y = pack2(l[2], l[3]);
    ((uint2*)g_akl)[idx] = out;
    #pragma unroll
    for (int i = 0; i < 4; i++) split_bf16(dv[i], h[i], l[i]);
    out.x = pack2(h[0], h[1]); out.y = pack2(h[2], h[3]);
    ((uint2*)g_avh)[idx] = out;
    out.x = pack2(l[0], l[1]); out.y = pack2(l[2], l[3]);
    ((uint2*)g_avl)[idx] = out;
    #pragma unroll
    for (int i = 0; i < 4; i++) split_bf16(dr[i], h[i], l[i]);
    out.x = pack2(h[0], h[1]); out.y = pack2(h[2], h[3]);
    ((uint2*)g_arh)[idx] = out;
    out.x = pack2(l[0], l[1]); out.y = pack2(l[2], l[3]);
    ((uint2*)g_arl)[idx] = out;
}

// ---------------------------------------------------------------------------
// bf16x3 mma.sync GEMM:  C[M,HD] = A[M,HD] @ Bt[HD,HD]^T  (Bt is [N,K] K-major)
// C = Ah*Bh + Ah*Bl + Al*Bh, fp32 accumulation. EPI: 0 = none, 1 = sigmoid.
// CTA 128x128x32, 256 threads, warp tile 64x32 (warps 2(M) x 4(N)).
// ---------------------------------------------------------------------------
template <int EPI>
__global__ void __launch_bounds__(256, 1)
gemm_bf16x3(const __nv_bfloat16* __restrict__ Ah,
            const __nv_bfloat16* __restrict__ Al,
            const __nv_bfloat16* __restrict__ Bh,
            const __nv_bfloat16* __restrict__ Bl,
            float* __restrict__ C) {
    extern __shared__ char smem[];
    uint32_t sbase = smem_u32(smem);
    int tid = threadIdx.x;
    int wid = tid >> 5;
    int lid = tid & 31;
    int mBase = blockIdx.y * BM;
    int nBase = blockIdx.x * BN;

    int wm = (wid & 1) * 64;       // warp M offset in CTA tile
    int wn = (wid >> 1) * 32;      // warp N offset

    // per-thread gmem load mapping: id = tid + i*256; row = id>>2, chunk = id&3
    // A: 512 16B-chunks per plane, 2 per thread. B: same.
    auto load_stage = [&](int buf, int k0) {
        uint32_t st = sbase + buf * STAGE_BYTES;
        #pragma unroll
        for (int i = 0; i < 2; i++) {
            int id = tid + i * 256;
            int r = id >> 2, c = id & 3;
            uint32_t so = (uint32_t)(r * PITCH + c * 16);
            size_t goA = (size_t)(mBase + r) * HD + k0 + c * 8;
            size_t goB = (size_t)(nBase + r) * HD + k0 + c * 8;
            cp_async16(st + so,             Ah + goA);
            cp_async16(st + PLANE + so,     Al + goA);
            cp_async16(st + 2 * PLANE + so, Bh + goB);
            cp_async16(st + 3 * PLANE + so, Bl + goB);
        }
    };

    float acc[4][4][4];   // [fm][fn][4]
    #pragma unroll
    for (int a = 0; a < 4; a++)
        #pragma unroll
        for (int b = 0; b < 4; b++)
            #pragma unroll
            for (int c = 0; c < 4; c++) acc[a][b][c] = 0.f;

    // prologue: prefetch STAGES-1 stages
    load_stage(0, 0);
    cp_commit();
    load_stage(1, BK);
    cp_commit();

    // lane-invariant pieces of smem addresses
    uint32_t aLane = (uint32_t)((wm + (lid & 15)) * PITCH + (lid >> 4) * 16);
    uint32_t bLane = (uint32_t)((wn + (lid >> 2)) * PITCH + (lid & 3) * 4);

    for (int s = 0; s < NITER; s++) {
        cp_wait<STAGES - 2>();
        __syncthreads();

        if (s + STAGES - 1 < NITER) {
            load_stage((s + STAGES - 1) % STAGES, (s + STAGES - 1) * BK);
            cp_commit();
        }

        uint32_t st = sbase + (s % STAGES) * STAGE_BYTES;
        uint32_t aH = st + aLane;
        uint32_t aL = aH + PLANE;
        uint32_t bH = st + 2 * PLANE + bLane;
        uint32_t bL = bH + PLANE;

        #pragma unroll
        for (int ks = 0; ks < 2; ks++) {
            uint32_t ah[4][4], al[4][4];
            #pragma unroll
            for (int fm = 0; fm < 4; fm++) {
                ldsm_x4(ah[fm], aH + fm * (16 * PITCH) + ks * 32);
                ldsm_x4(al[fm], aL + fm * (16 * PITCH) + ks * 32);
            }
            #pragma unroll
            for (int fn = 0; fn < 4; fn++) {
                uint32_t bh[2], bl[2];
                uint32_t bo = fn * (8 * PITCH) + ks * 32;
                bh[0] = lds32(bH + bo);
                bh[1] = lds32(bH + bo + 16);
                bl[0] = lds32(bL + bo);
                bl[1] = lds32(bL + bo + 16);
                #pragma unroll
                for (int fm = 0; fm < 4; fm++) {
                    mma16816(acc[fm][fn], ah[fm], bh);
                    mma16816(acc[fm][fn], ah[fm], bl);
                    mma16816(acc[fm][fn], al[fm], bh);
                }
            }
        }
        __syncthreads();
    }

    // epilogue
    int gid = lid >> 2, tig = lid & 3;
    #pragma unroll
    for (int fm = 0; fm < 4; fm++) {
        int row0 = mBase + wm + fm * 16 + gid;
        #pragma unroll
        for (int fn = 0; fn < 4; fn++) {
            int col = nBase + wn + fn * 8 + tig * 2;
            float2 v0 = make_float2(acc[fm][fn][0], acc[fm][fn][1]);
            float2 v1 = make_float2(acc[fm][fn][2], acc[fm][fn][3]);
            if (EPI == 1) {
                v0.x = 1.f / (1.f + __expf(-v0.x));
                v0.y = 1.f / (1.f + __expf(-v0.y));
                v1.x = 1.f / (1.f + __expf(-v1.x));
                v1.y = 1.f / (1.f + __expf(-v1.y));
            }
            *(float2*)(C + (size_t)row0 * HD + col) = v0;
            *(float2*)(C + (size_t)(row0 + 8) * HD + col) = v1;
        }
    }
}

// ---------------------------------------------------------------------------
// WKV scan: one thread per (b, d). Fuses p = r * rwkv, writes bf16 hi/lo planes
// (into g_akh/g_akl, which are free after the k GEMM).
// ---------------------------------------------------------------------------
__global__ void wkv_kernel(const float* __restrict__ time_decay,
                           const float* __restrict__ time_first) {
    int idx = blockIdx.x * blockDim.x + threadIdx.x;   // 0..8191
    int b = idx / HD;
    int d = idx % HD;

    float td = -__expf(time_decay[d]);
    float tf = time_first[d];

    float num = 0.f, den = 0.f, mx = -1e38f;
    size_t base = (size_t)b * TLEN * HD + d;

    float kt = g_k[base];
    float vt = g_v[base];
    float rt = g_r[base];

    for (int t = 0; t < TLEN; t++) {
        size_t off = base + (size_t)t * HD;
        float ktn = 0.f, vtn = 0.f, rtn = 0.f;
        if (t + 1 < TLEN) {
            ktn = g_k[off + HD];
            vtn = g_v[off + HD];
            rtn = g_r[off + HD];
        }

        float mfo = fmaxf(mx, kt + tf);
        float e1  = __expf(mx - mfo);
        float e2  = __expf(kt + tf - mfo);
        float out = (e1 * num + e2 * vt) / (e1 * den + e2);

        float mfs = fmaxf(mx + td, kt);
        float e1s = __expf(mx + td - mfs);
        float e2s = __expf(kt - mfs);
        num = e1s * num + e2s * vt;
        den = e1s * den + e2s;
        mx  = mfs;

        float pval = out * rt;
        __nv_bfloat16 h, l;
        split_bf16(pval, h, l);
        g_akh[off] = h;
        g_akl[off] = l;

        kt = ktn;
        vt = vtn;
        rt = rtn;
    }
}

// ---------------------------------------------------------------------------
// Launch
// ---------------------------------------------------------------------------
extern "C" void kernel_launch(void* const* d_in, const int* in_sizes, int n_in,
                              void* d_out, int out_size) {
    const float* hidden = (const float*)d_in[0];
    const float* time_decay = (const float*)d_in[1];
    const float* time_first = (const float*)d_in[2];
    const float* tmk = (const float*)d_in[3];
    const float* tmv = (const float*)d_in[4];
    const float* tmr = (const float*)d_in[5];
    const float* Wk = (const float*)d_in[6];
    const float* Wv = (const float*)d_in[7];
    const float* Wr = (const float*)d_in[8];
    const float* Wo = (const float*)d_in[9];

    __nv_bfloat16 *akh, *akl, *avh, *avl, *arh, *arl;
    __nv_bfloat16 *wkh, *wkl, *wvh, *wvl, *wrh, *wrl, *woh, *wol;
    float *kb, *vb, *rb;
    cudaGetSymbolAddress((void**)&akh, g_akh);
    cudaGetSymbolAddress((void**)&akl, g_akl);
    cudaGetSymbolAddress((void**)&avh, g_avh);
    cudaGetSymbolAddress((void**)&avl, g_avl);
    cudaGetSymbolAddress((void**)&arh, g_arh);
    cudaGetSymbolAddress((void**)&arl, g_arl);
    cudaGetSymbolAddress((void**)&wkh, g_wkh);
    cudaGetSymbolAddress((void**)&wkl, g_wkl);
    cudaGetSymbolAddress((void**)&wvh, g_wvh);
    cudaGetSymbolAddress((void**)&wvl, g_wvl);
    cudaGetSymbolAddress((void**)&wrh, g_wrh);
    cudaGetSymbolAddress((void**)&wrl, g_wrl);
    cudaGetSymbolAddress((void**)&woh, g_woh);
    cudaGetSymbolAddress((void**)&wol, g_wol);
    cudaGetSymbolAddress((void**)&kb, g_k);
    cudaGetSymbolAddress((void**)&vb, g_v);
    cudaGetSymbolAddress((void**)&rb, g_r);

    cudaFuncSetAttribute(gemm_bf16x3<0>, cudaFuncAttributeMaxDynamicSharedMemorySize, SMEM_GEMM);
    cudaFuncSetAttribute(gemm_bf16x3<1>, cudaFuncAttributeMaxDynamicSharedMemorySize, SMEM_GEMM);

    // 1. weight transpose + split
    dim3 tgrid(HD / 32, HD / 32);
    transpose_split<<<tgrid, 256>>>(Wk, wkh, wkl);
    transpose_split<<<tgrid, 256>>>(Wv, wvh, wvl);
    transpose_split<<<tgrid, 256>>>(Wr, wrh, wrl);
    transpose_split<<<tgrid, 256>>>(Wo, woh, wol);

    // 2. mixes (hi/lo bf16 planes)
    mix_kernel<<<(int)(TOT / 4 / 256), 256>>>(hidden, tmk, tmv, tmr);

    // 3. three input GEMMs (mma.sync bf16x3)
    dim3 grid(HD / BN, MROWS / BM);   // (16, 64)
    gemm_bf16x3<0><<<grid, 256, SMEM_GEMM>>>(akh, akl, wkh, wkl, kb);
    gemm_bf16x3<0><<<grid, 256, SMEM_GEMM>>>(avh, avl, wvh, wvl, vb);
    gemm_bf16x3<1><<<grid, 256, SMEM_GEMM>>>(arh, arl, wrh, wrl, rb);

    // 4. WKV scan (fused r*), writes p hi/lo into g_akh/g_akl
    wkv_kernel<<<MROWS / 256, 256>>>(time_decay, time_first);

    // 5. output GEMM
    gemm_bf16x3<0><<<grid, 256, SMEM_GEMM>>>(akh, akl, woh, wol, (float*)d_out);
}

// round 5
// speedup vs baseline: 2.6879x; 1.3345x over previous
#include <cuda_runtime.h>
#include <cuda_fp16.h>
#include <cstdint>
#include <math.h>

// ---------------------------------------------------------------------------
// Problem dims (fixed)
// ---------------------------------------------------------------------------
constexpr int BATCH = 4;
constexpr int TLEN  = 2048;
constexpr int HD    = 2048;                  // N = K = 2048
constexpr int MROWS = BATCH * TLEN;          // 8192
constexpr size_t TOT = (size_t)MROWS * HD;   // 16,777,216

// GEMM tiling: CTA 128x128x64, 8 warps (2M x 4N), warp tile 64x32
constexpr int BM = 128;
constexpr int BN = 128;
constexpr int BK = 64;
constexpr int NITER = HD / BK;               // 32
constexpr int STAGES = 3;
constexpr int PITCH = 144;                   // 64 fp16 = 128B data + 16B pad
constexpr int PLANE = 128 * PITCH;           // 18432 B
constexpr int STAGE_BYTES = 3 * PLANE;       // Ah, Al, Bh = 55296
constexpr int SMEM_GEMM = STAGES * STAGE_BYTES;  // 165888

// ---------------------------------------------------------------------------
// Scratch (device globals: allocation-free per harness rules)
// ---------------------------------------------------------------------------
__device__ __align__(256) __half g_akh[TOT];  // key-mix hi (reused as p hi)
__device__ __align__(256) __half g_akl[TOT];  // key-mix lo (reused as p lo)
__device__ __align__(256) __half g_avh[TOT];
__device__ __align__(256) __half g_avl[TOT];
__device__ __align__(256) __half g_arh[TOT];
__device__ __align__(256) __half g_arl[TOT];
__device__ __align__(256) float g_k[TOT];
__device__ __align__(256) float g_v[TOT];
__device__ __align__(256) float g_r[TOT];
// transposed weights: [N=2048, K=2048] fp16, K-major
__device__ __align__(256) __half g_wk[HD * HD];
__device__ __align__(256) __half g_wv[HD * HD];
__device__ __align__(256) __half g_wr[HD * HD];
__device__ __align__(256) __half g_wo[HD * HD];

// ---------------------------------------------------------------------------
// PTX helpers (base sm_103 target: cp.async, ldmatrix, mma.sync)
// ---------------------------------------------------------------------------
__device__ __forceinline__ uint32_t smem_u32(const void* p) {
    uint32_t a;
    asm("{ .reg .u64 t; cvta.to.shared.u64 t, %1; cvt.u32.u64 %0, t; }"
        : "=r"(a) : "l"(p));
    return a;
}

__device__ __forceinline__ void cp_async16(uint32_t s, const void* g) {
    asm volatile("cp.async.cg.shared.global [%0], [%1], 16;" :: "r"(s), "l"(g));
}
__device__ __forceinline__ void cp_commit() {
    asm volatile("cp.async.commit_group;" ::: "memory");
}
template <int N>
__device__ __forceinline__ void cp_wait() {
    asm volatile("cp.async.wait_group %0;" :: "n"(N) : "memory");
}

__device__ __forceinline__ void ldsm_x4(uint32_t* r, uint32_t addr) {
    asm volatile("ldmatrix.sync.aligned.m8n8.x4.shared.b16 {%0,%1,%2,%3}, [%4];"
        : "=r"(r[0]), "=r"(r[1]), "=r"(r[2]), "=r"(r[3]) : "r"(addr));
}

__device__ __forceinline__ uint32_t lds32(uint32_t addr) {
    uint32_t v;
    asm volatile("ld.shared.b32 %0, [%1];" : "=r"(v) : "r"(addr));
    return v;
}

// mma.sync m16n8k16 fp16 -> fp32, D += A*B
__device__ __forceinline__ void mma16816(float* d, const uint32_t* a, const uint32_t* b) {
    asm volatile(
        "mma.sync.aligned.m16n8k16.row.col.f32.f16.f16.f32 "
        "{%0,%1,%2,%3}, {%4,%5,%6,%7}, {%8,%9}, {%0,%1,%2,%3};"
        : "+f"(d[0]), "+f"(d[1]), "+f"(d[2]), "+f"(d[3])
        : "r"(a[0]), "r"(a[1]), "r"(a[2]), "r"(a[3]), "r"(b[0]), "r"(b[1]));
}

// ---------------------------------------------------------------------------
// fp16 split helpers
// ---------------------------------------------------------------------------
__device__ __forceinline__ void split_h(float v, __half& h, __half& l) {
    h = __float2half_rn(v);
    l = __float2half_rn(v - __half2float(h));
}
__device__ __forceinline__ uint32_t pack2h(__half a, __half b) {
    __half2 t(a, b);
    return *(uint32_t*)&t;
}

// ---------------------------------------------------------------------------
// Weight transpose:  W[K,N] fp32 -> T[N,K] fp16
// ---------------------------------------------------------------------------
__global__ void transpose_half(const float* __restrict__ W,
                               __half* __restrict__ T) {
    __shared__ float tile[32][33];
    int tx = threadIdx.x & 31;
    int ty0 = threadIdx.x >> 5;          // 0..7
    int bx = blockIdx.x * 32;            // n base
    int by = blockIdx.y * 32;            // k base
    #pragma unroll
    for (int i = 0; i < 32; i += 8)
        tile[ty0 + i][tx] = W[(size_t)(by + ty0 + i) * HD + bx + tx];
    __syncthreads();
    #pragma unroll
    for (int i = 0; i < 32; i += 8)
        T[(size_t)(bx + ty0 + i) * HD + by + tx] = __float2half_rn(tile[tx][ty0 + i]);
}

// ---------------------------------------------------------------------------
// Time-shift + three mixes -> six fp16 planes (hi/lo for k, v, r)
// ---------------------------------------------------------------------------
__global__ void mix_kernel(const float* __restrict__ hidden,
                           const float* __restrict__ tmk,
                           const float* __restrict__ tmv,
                           const float* __restrict__ tmr) {
    int idx = blockIdx.x * blockDim.x + threadIdx.x;  // float4 index
    constexpr int HV = HD / 4;
    int row = idx / HV;
    int hv  = idx % HV;
    bool hasPrev = (row % TLEN) != 0;

    const float4* h4 = (const float4*)hidden;
    float4 cur  = h4[idx];
    float4 prev = hasPrev ? h4[idx - HV] : make_float4(0.f, 0.f, 0.f, 0.f);

    float4 mk = ((const float4*)tmk)[hv];
    float4 mv = ((const float4*)tmv)[hv];
    float4 mr = ((const float4*)tmr)[hv];

    float c[4] = {cur.x, cur.y, cur.z, cur.w};
    float p[4] = {prev.x, prev.y, prev.z, prev.w};
    float k_[4] = {mk.x, mk.y, mk.z, mk.w};
    float v_[4] = {mv.x, mv.y, mv.z, mv.w};
    float r_[4] = {mr.x, mr.y, mr.z, mr.w};
    float dk[4], dv[4], dr[4];
    #pragma unroll
    for (int i = 0; i < 4; i++) {
        dk[i] = p[i] + k_[i] * (c[i] - p[i]);
        dv[i] = p[i] + v_[i] * (c[i] - p[i]);
        dr[i] = p[i] + r_[i] * (c[i] - p[i]);
    }

    __half h[4], l[4];
    uint2 out;
    #pragma unroll
    for (int i = 0; i < 4; i++) split_h(dk[i], h[i], l[i]);
    out.x = pack2h(h[0], h[1]); out.y = pack2h(h[2], h[3]);
    ((uint2*)g_akh)[idx] = out;
    out.x = pack2h(l[0], l[1]); out.y = pack2h(l[2], l[3]);
    ((uint2*)g_akl)[idx] = out;
    #pragma unroll
    for (int i = 0; i < 4; i++) split_h(dv[i], h[i], l[i]);
    out.x = pack2h(h[0], h[1]); out.y = pack2h(h[2], h[3]);
    ((uint2*)g_avh)[idx] = out;
    out.x = pack2h(l[0], l[1]); out.y = pack2h(l[2], l[3]);
    ((uint2*)g_avl)[idx] = out;
    #pragma unroll
    for (int i = 0; i < 4; i++) split_h(dr[i], h[i], l[i]);
    out.x = pack2h(h[0], h[1]); out.y = pack2h(h[2], h[3]);
    ((uint2*)g_arh)[idx] = out;
    out.x = pack2h(l[0], l[1]); out.y = pack2h(l[2], l[3]);
    ((uint2*)g_arl)[idx] = out;
}

// ---------------------------------------------------------------------------
// fp16x2 mma.sync GEMM:  C[M,HD] = (Ah+Al)[M,HD] @ Bt[HD,HD]^T
// (Bt is [N,K] K-major fp16).  fp32 accumulation.  EPI: 0 = none, 1 = sigmoid.
// CTA 128x128x64, 256 threads, warp tile 64x32 (warps 2(M) x 4(N)), 3 stages.
// ---------------------------------------------------------------------------
template <int EPI>
__global__ void __launch_bounds__(256, 1)
gemm_f16x2(const __half* __restrict__ Ah,
           const __half* __restrict__ Al,
           const __half* __restrict__ Bh,
           float* __restrict__ C) {
    extern __shared__ char smem[];
    uint32_t sbase = smem_u32(smem);
    int tid = threadIdx.x;
    int wid = tid >> 5;
    int lid = tid & 31;
    int mBase = blockIdx.y * BM;
    int nBase = blockIdx.x * BN;

    int wm = (wid & 1) * 64;       // warp M offset
    int wn = (wid >> 1) * 32;      // warp N offset

    // gmem->smem: 3 planes x 128 rows x 8 chunks(16B) = 3072 chunks, 12/thread
    auto load_stage = [&](int buf, int k0) {
        uint32_t st = sbase + buf * STAGE_BYTES;
        #pragma unroll
        for (int i = 0; i < 4; i++) {
            int id = tid + i * 256;
            int r = id >> 3, c = id & 7;
            uint32_t so = (uint32_t)(r * PITCH + c * 16);
            size_t goA = (size_t)(mBase + r) * HD + k0 + c * 8;
            size_t goB = (size_t)(nBase + r) * HD + k0 + c * 8;
            cp_async16(st + so,             Ah + goA);
            cp_async16(st + PLANE + so,     Al + goA);
            cp_async16(st + 2 * PLANE + so, Bh + goB);
        }
    };

    float acc[4][4][4];
    #pragma unroll
    for (int a = 0; a < 4; a++)
        #pragma unroll
        for (int b = 0; b < 4; b++)
            #pragma unroll
            for (int c = 0; c < 4; c++) acc[a][b][c] = 0.f;

    load_stage(0, 0);
    cp_commit();
    load_stage(1, BK);
    cp_commit();

    uint32_t aLane = (uint32_t)((wm + (lid & 15)) * PITCH + (lid >> 4) * 16);
    uint32_t bLane = (uint32_t)((wn + (lid >> 2)) * PITCH + (lid & 3) * 4);

    for (int s = 0; s < NITER; s++) {
        cp_wait<STAGES - 2>();
        __syncthreads();

        if (s + 2 < NITER) {
            load_stage((s + 2) % STAGES, (s + 2) * BK);
            cp_commit();
        }

        uint32_t st = sbase + (s % STAGES) * STAGE_BYTES;
        uint32_t aH = st + aLane;
        uint32_t aL = aH + PLANE;
        uint32_t bB = st + 2 * PLANE + bLane;

        #pragma unroll
        for (int ks = 0; ks < 4; ks++) {     // 4 x k16 per stage
            uint32_t ah[4][4], al[4][4], bh[4][2];
            #pragma unroll
            for (int fm = 0; fm < 4; fm++) {
                ldsm_x4(ah[fm], aH + fm * (16 * PITCH) + ks * 32);
                ldsm_x4(al[fm], aL + fm * (16 * PITCH) + ks * 32);
            }
            #pragma unroll
            for (int fn = 0; fn < 4; fn++) {
                uint32_t bo = fn * (8 * PITCH) + ks * 32;
                bh[fn][0] = lds32(bB + bo);
                bh[fn][1] = lds32(bB + bo + 16);
            }
            // term-major: accumulator reuse distance = 16 MMAs (no serial chains)
            #pragma unroll
            for (int fm = 0; fm < 4; fm++)
                #pragma unroll
                for (int fn = 0; fn < 4; fn++)
                    mma16816(acc[fm][fn], ah[fm], bh[fn]);
            #pragma unroll
            for (int fm = 0; fm < 4; fm++)
                #pragma unroll
                for (int fn = 0; fn < 4; fn++)
                    mma16816(acc[fm][fn], al[fm], bh[fn]);
        }
    }

    // epilogue
    int gid = lid >> 2, tig = lid & 3;
    #pragma unroll
    for (int fm = 0; fm < 4; fm++) {
        int row0 = mBase + wm + fm * 16 + gid;
        #pragma unroll
        for (int fn = 0; fn < 4; fn++) {
            int col = nBase + wn + fn * 8 + tig * 2;
            float2 v0 = make_float2(acc[fm][fn][0], acc[fm][fn][1]);
            float2 v1 = make_float2(acc[fm][fn][2], acc[fm][fn][3]);
            if (EPI == 1) {
                v0.x = 1.f / (1.f + __expf(-v0.x));
                v0.y = 1.f / (1.f + __expf(-v0.y));
                v1.x = 1.f / (1.f + __expf(-v1.x));
                v1.y = 1.f / (1.f + __expf(-v1.y));
            }
            *(float2*)(C + (size_t)row0 * HD + col) = v0;
            *(float2*)(C + (size_t)(row0 + 8) * HD + col) = v1;
        }
    }
}

// ---------------------------------------------------------------------------
// WKV scan: one thread per (b, d). Fuses p = r * rwkv, writes fp16 hi/lo planes
// (into g_akh/g_akl, free after the k GEMM). 64-thread blocks -> 128 CTAs
// spread over more SMs.
// ---------------------------------------------------------------------------
__global__ void wkv_kernel(const float* __restrict__ time_decay,
                           const float* __restrict__ time_first) {
    int idx = blockIdx.x * blockDim.x + threadIdx.x;   // 0..8191
    int b = idx / HD;
    int d = idx % HD;

    float td = -__expf(time_decay[d]);
    float tf = time_first[d];

    float num = 0.f, den = 0.f, mx = -1e38f;
    size_t base = (size_t)b * TLEN * HD + d;

    float kt = g_k[base];
    float vt = g_v[base];
    float rt = g_r[base];

    for (int t = 0; t < TLEN; t++) {
        size_t off = base + (size_t)t * HD;
        float ktn = 0.f, vtn = 0.f, rtn = 0.f;
        if (t + 1 < TLEN) {
            ktn = g_k[off + HD];
            vtn = g_v[off + HD];
            rtn = g_r[off + HD];
        }

        float mfo = fmaxf(mx, kt + tf);
        float e1  = __expf(mx - mfo);
        float e2  = __expf(kt + tf - mfo);
        float out = (e1 * num + e2 * vt) / (e1 * den + e2);

        float mfs = fmaxf(mx + td, kt);
        float e1s = __expf(mx + td - mfs);
        float e2s = __expf(kt - mfs);
        num = e1s * num + e2s * vt;
        den = e1s * den + e2s;
        mx  = mfs;

        float pval = out * rt;
        __half h, l;
        split_h(pval, h, l);
        g_akh[off] = h;
        g_akl[off] = l;

        kt = ktn;
        vt = vtn;
        rt = rtn;
    }
}

// ---------------------------------------------------------------------------
// Launch
// ---------------------------------------------------------------------------
extern "C" void kernel_launch(void* const* d_in, const int* in_sizes, int n_in,
                              void* d_out, int out_size) {
    const float* hidden = (const float*)d_in[0];
    const float* time_decay = (const float*)d_in[1];
    const float* time_first = (const float*)d_in[2];
    const float* tmk = (const float*)d_in[3];
    const float* tmv = (const float*)d_in[4];
    const float* tmr = (const float*)d_in[5];
    const float* Wk = (const float*)d_in[6];
    const float* Wv = (const float*)d_in[7];
    const float* Wr = (const float*)d_in[8];
    const float* Wo = (const float*)d_in[9];

    __half *akh, *akl, *avh, *avl, *arh, *arl;
    __half *wk, *wv, *wr, *wo;
    float *kb, *vb, *rb;
    cudaGetSymbolAddress((void**)&akh, g_akh);
    cudaGetSymbolAddress((void**)&akl, g_akl);
    cudaGetSymbolAddress((void**)&avh, g_avh);
    cudaGetSymbolAddress((void**)&avl, g_avl);
    cudaGetSymbolAddress((void**)&arh, g_arh);
    cudaGetSymbolAddress((void**)&arl, g_arl);
    cudaGetSymbolAddress((void**)&wk, g_wk);
    cudaGetSymbolAddress((void**)&wv, g_wv);
    cudaGetSymbolAddress((void**)&wr, g_wr);
    cudaGetSymbolAddress((void**)&wo, g_wo);
    cudaGetSymbolAddress((void**)&kb, g_k);
    cudaGetSymbolAddress((void**)&vb, g_v);
    cudaGetSymbolAddress((void**)&rb, g_r);

    cudaFuncSetAttribute(gemm_f16x2<0>, cudaFuncAttributeMaxDynamicSharedMemorySize, SMEM_GEMM);
    cudaFuncSetAttribute(gemm_f16x2<1>, cudaFuncAttributeMaxDynamicSharedMemorySize, SMEM_GEMM);

    // 1. weight transposes (fp16, single plane)
    dim3 tgrid(HD / 32, HD / 32);
    transpose_half<<<tgrid, 256>>>(Wk, wk);
    transpose_half<<<tgrid, 256>>>(Wv, wv);
    transpose_half<<<tgrid, 256>>>(Wr, wr);
    transpose_half<<<tgrid, 256>>>(Wo, wo);

    // 2. mixes (hi/lo fp16 planes)
    mix_kernel<<<(int)(TOT / 4 / 256), 256>>>(hidden, tmk, tmv, tmr);

    // 3. three input GEMMs (mma.sync fp16x2)
    dim3 grid(HD / BN, MROWS / BM);   // (16, 64)
    gemm_f16x2<0><<<grid, 256, SMEM_GEMM>>>(akh, akl, wk, kb);
    gemm_f16x2<0><<<grid, 256, SMEM_GEMM>>>(avh, avl, wv, vb);
    gemm_f16x2<1><<<grid, 256, SMEM_GEMM>>>(arh, arl, wr, rb);

    // 4. WKV scan (fused r*), writes p hi/lo into g_akh/g_akl
    wkv_kernel<<<128, 64>>>(time_decay, time_first);

    // 5. output GEMM
    gemm_f16x2<0><<<grid, 256, SMEM_GEMM>>>(akh, akl, wo, (float*)d_out);
}

// round 6
// speedup vs baseline: 2.8754x; 1.0698x over previous
#include <cuda_runtime.h>
#include <cuda_fp16.h>
#include <cstdint>
#include <math.h>

// ---------------------------------------------------------------------------
// Problem dims (fixed)
// ---------------------------------------------------------------------------
constexpr int BATCH = 4;
constexpr int TLEN  = 2048;
constexpr int HD    = 2048;                  // N = K = 2048
constexpr int MROWS = BATCH * TLEN;          // 8192
constexpr size_t TOT = (size_t)MROWS * HD;   // 16,777,216

// GEMM tiling: CTA 128x128x64, 8 warps (2M x 4N), warp tile 64x32
constexpr int BM = 128;
constexpr int BN = 128;
constexpr int BK = 64;
constexpr int NITER = HD / BK;               // 32
constexpr int STAGES = 4;
constexpr int PITCH = 144;                   // 64 fp16 = 128B data + 16B pad
constexpr int PLANE = 128 * PITCH;           // 18432 B
constexpr int STAGE_BYTES = 2 * PLANE;       // A, B = 36864
constexpr int SMEM_GEMM = STAGES * STAGE_BYTES;  // 147456

// ---------------------------------------------------------------------------
// Scratch (device globals: allocation-free per harness rules)
// ---------------------------------------------------------------------------
__device__ __align__(256) __half g_ak[TOT];   // key-mix (reused as p = r*rwkv)
__device__ __align__(256) __half g_av[TOT];
__device__ __align__(256) __half g_ar[TOT];
__device__ __align__(256) float g_k[TOT];
__device__ __align__(256) float g_v[TOT];
__device__ __align__(256) float g_r[TOT];
// transposed weights: [N=2048, K=2048] fp16, K-major
__device__ __align__(256) __half g_wk[HD * HD];
__device__ __align__(256) __half g_wv[HD * HD];
__device__ __align__(256) __half g_wr[HD * HD];
__device__ __align__(256) __half g_wo[HD * HD];

// ---------------------------------------------------------------------------
// PTX helpers (base sm_103 target: cp.async, ldmatrix, mma.sync)
// ---------------------------------------------------------------------------
__device__ __forceinline__ uint32_t smem_u32(const void* p) {
    uint32_t a;
    asm("{ .reg .u64 t; cvta.to.shared.u64 t, %1; cvt.u32.u64 %0, t; }"
        : "=r"(a) : "l"(p));
    return a;
}

__device__ __forceinline__ void cp_async16(uint32_t s, const void* g) {
    asm volatile("cp.async.cg.shared.global [%0], [%1], 16;" :: "r"(s), "l"(g));
}
__device__ __forceinline__ void cp_commit() {
    asm volatile("cp.async.commit_group;" ::: "memory");
}
template <int N>
__device__ __forceinline__ void cp_wait() {
    asm volatile("cp.async.wait_group %0;" :: "n"(N) : "memory");
}

__device__ __forceinline__ void ldsm_x4(uint32_t* r, uint32_t addr) {
    asm volatile("ldmatrix.sync.aligned.m8n8.x4.shared.b16 {%0,%1,%2,%3}, [%4];"
        : "=r"(r[0]), "=r"(r[1]), "=r"(r[2]), "=r"(r[3]) : "r"(addr));
}

__device__ __forceinline__ uint32_t lds32(uint32_t addr) {
    uint32_t v;
    asm volatile("ld.shared.b32 %0, [%1];" : "=r"(v) : "r"(addr));
    return v;
}

// mma.sync m16n8k16 fp16 -> fp32, D += A*B
__device__ __forceinline__ void mma16816(float* d, const uint32_t* a, const uint32_t* b) {
    asm volatile(
        "mma.sync.aligned.m16n8k16.row.col.f32.f16.f16.f32 "
        "{%0,%1,%2,%3}, {%4,%5,%6,%7}, {%8,%9}, {%0,%1,%2,%3};"
        : "+f"(d[0]), "+f"(d[1]), "+f"(d[2]), "+f"(d[3])
        : "r"(a[0]), "r"(a[1]), "r"(a[2]), "r"(a[3]), "r"(b[0]), "r"(b[1]));
}

__device__ __forceinline__ uint32_t pack2h(__half a, __half b) {
    __half2 t(a, b);
    return *(uint32_t*)&t;
}

// ---------------------------------------------------------------------------
// Weight transpose:  W[K,N] fp32 -> T[N,K] fp16
// ---------------------------------------------------------------------------
__global__ void transpose_half(const float* __restrict__ W,
                               __half* __restrict__ T) {
    __shared__ float tile[32][33];
    int tx = threadIdx.x & 31;
    int ty0 = threadIdx.x >> 5;          // 0..7
    int bx = blockIdx.x * 32;            // n base
    int by = blockIdx.y * 32;            // k base
    #pragma unroll
    for (int i = 0; i < 32; i += 8)
        tile[ty0 + i][tx] = W[(size_t)(by + ty0 + i) * HD + bx + tx];
    __syncthreads();
    #pragma unroll
    for (int i = 0; i < 32; i += 8)
        T[(size_t)(bx + ty0 + i) * HD + by + tx] = __float2half_rn(tile[tx][ty0 + i]);
}

// ---------------------------------------------------------------------------
// Time-shift + three mixes -> three fp16 planes
// ---------------------------------------------------------------------------
__global__ void mix_kernel(const float* __restrict__ hidden,
                           const float* __restrict__ tmk,
                           const float* __restrict__ tmv,
                           const float* __restrict__ tmr) {
    int idx = blockIdx.x * blockDim.x + threadIdx.x;  // float4 index
    constexpr int HV = HD / 4;
    int row = idx / HV;
    int hv  = idx % HV;
    bool hasPrev = (row % TLEN) != 0;

    const float4* h4 = (const float4*)hidden;
    float4 cur  = h4[idx];
    float4 prev = hasPrev ? h4[idx - HV] : make_float4(0.f, 0.f, 0.f, 0.f);

    float4 mk = ((const float4*)tmk)[hv];
    float4 mv = ((const float4*)tmv)[hv];
    float4 mr = ((const float4*)tmr)[hv];

    float c[4] = {cur.x, cur.y, cur.z, cur.w};
    float p[4] = {prev.x, prev.y, prev.z, prev.w};
    float k_[4] = {mk.x, mk.y, mk.z, mk.w};
    float v_[4] = {mv.x, mv.y, mv.z, mv.w};
    float r_[4] = {mr.x, mr.y, mr.z, mr.w};

    __half hk[4], hv_[4], hr[4];
    #pragma unroll
    for (int i = 0; i < 4; i++) {
        hk[i]  = __float2half_rn(p[i] + k_[i] * (c[i] - p[i]));
        hv_[i] = __float2half_rn(p[i] + v_[i] * (c[i] - p[i]));
        hr[i]  = __float2half_rn(p[i] + r_[i] * (c[i] - p[i]));
    }

    uint2 out;
    out.x = pack2h(hk[0], hk[1]);  out.y = pack2h(hk[2], hk[3]);
    ((uint2*)g_ak)[idx] = out;
    out.x = pack2h(hv_[0], hv_[1]); out.y = pack2h(hv_[2], hv_[3]);
    ((uint2*)g_av)[idx] = out;
    out.x = pack2h(hr[0], hr[1]);  out.y = pack2h(hr[2], hr[3]);
    ((uint2*)g_ar)[idx] = out;
}

// ---------------------------------------------------------------------------
// fp16 mma.sync GEMM:  C[M,HD] = A[M,HD] @ Bt[HD,HD]^T  (Bt is [N,K] K-major)
// fp32 accumulation.  EPI: 0 = none, 1 = sigmoid.
// CTA 128x128x64, 256 threads, warp tile 64x32 (warps 2(M) x 4(N)), 4 stages.
// ---------------------------------------------------------------------------
template <int EPI>
__global__ void __launch_bounds__(256, 1)
gemm_f16(const __half* __restrict__ A,
         const __half* __restrict__ B,
         float* __restrict__ C) {
    extern __shared__ char smem[];
    uint32_t sbase = smem_u32(smem);
    int tid = threadIdx.x;
    int wid = tid >> 5;
    int lid = tid & 31;
    int mBase = blockIdx.y * BM;
    int nBase = blockIdx.x * BN;

    int wm = (wid & 1) * 64;       // warp M offset
    int wn = (wid >> 1) * 32;      // warp N offset

    // gmem->smem: 2 planes x 128 rows x 8 chunks(16B) = 2048 chunks, 8/thread
    auto load_stage = [&](int buf, int k0) {
        uint32_t st = sbase + buf * STAGE_BYTES;
        #pragma unroll
        for (int i = 0; i < 4; i++) {
            int id = tid + i * 256;
            int r = id >> 3, c = id & 7;
            uint32_t so = (uint32_t)(r * PITCH + c * 16);
            cp_async16(st + so,         A + (size_t)(mBase + r) * HD + k0 + c * 8);
            cp_async16(st + PLANE + so, B + (size_t)(nBase + r) * HD + k0 + c * 8);
        }
    };

    float acc[4][4][4];
    #pragma unroll
    for (int a = 0; a < 4; a++)
        #pragma unroll
        for (int b = 0; b < 4; b++)
            #pragma unroll
            for (int c = 0; c < 4; c++) acc[a][b][c] = 0.f;

    load_stage(0, 0);
    cp_commit();
    load_stage(1, BK);
    cp_commit();
    load_stage(2, 2 * BK);
    cp_commit();

    uint32_t aLane = (uint32_t)((wm + (lid & 15)) * PITCH + (lid >> 4) * 16);
    uint32_t bLane = (uint32_t)((wn + (lid >> 2)) * PITCH + (lid & 3) * 4);

    for (int s = 0; s < NITER; s++) {
        cp_wait<STAGES - 2>();
        __syncthreads();

        if (s + STAGES - 1 < NITER) {
            load_stage((s + STAGES - 1) % STAGES, (s + STAGES - 1) * BK);
            cp_commit();
        }

        uint32_t st = sbase + (s % STAGES) * STAGE_BYTES;
        uint32_t aA = st + aLane;
        uint32_t bB = st + PLANE + bLane;

        #pragma unroll
        for (int ks = 0; ks < 4; ks++) {     // 4 x k16 per stage
            uint32_t ah[4][4], bh[4][2];
            #pragma unroll
            for (int fm = 0; fm < 4; fm++)
                ldsm_x4(ah[fm], aA + fm * (16 * PITCH) + ks * 32);
            #pragma unroll
            for (int fn = 0; fn < 4; fn++) {
                uint32_t bo = fn * (8 * PITCH) + ks * 32;
                bh[fn][0] = lds32(bB + bo);
                bh[fn][1] = lds32(bB + bo + 16);
            }
            #pragma unroll
            for (int fm = 0; fm < 4; fm++)
                #pragma unroll
                for (int fn = 0; fn < 4; fn++)
                    mma16816(acc[fm][fn], ah[fm], bh[fn]);
        }
    }

    // epilogue
    int gid = lid >> 2, tig = lid & 3;
    #pragma unroll
    for (int fm = 0; fm < 4; fm++) {
        int row0 = mBase + wm + fm * 16 + gid;
        #pragma unroll
        for (int fn = 0; fn < 4; fn++) {
            int col = nBase + wn + fn * 8 + tig * 2;
            float2 v0 = make_float2(acc[fm][fn][0], acc[fm][fn][1]);
            float2 v1 = make_float2(acc[fm][fn][2], acc[fm][fn][3]);
            if (EPI == 1) {
                v0.x = 1.f / (1.f + __expf(-v0.x));
                v0.y = 1.f / (1.f + __expf(-v0.y));
                v1.x = 1.f / (1.f + __expf(-v1.x));
                v1.y = 1.f / (1.f + __expf(-v1.y));
            }
            *(float2*)(C + (size_t)row0 * HD + col) = v0;
            *(float2*)(C + (size_t)(row0 + 8) * HD + col) = v1;
        }
    }
}

// ---------------------------------------------------------------------------
// WKV scan: one thread per (b, d). Fuses p = r * rwkv, writes fp16 plane
// (into g_ak, free after the k GEMM).
// ---------------------------------------------------------------------------
__global__ void wkv_kernel(const float* __restrict__ time_decay,
                           const float* __restrict__ time_first) {
    int idx = blockIdx.x * blockDim.x + threadIdx.x;   // 0..8191
    int b = idx / HD;
    int d = idx % HD;

    float td = -__expf(time_decay[d]);
    float tf = time_first[d];

    float num = 0.f, den = 0.f, mx = -1e38f;
    size_t base = (size_t)b * TLEN * HD + d;

    float kt = g_k[base];
    float vt = g_v[base];
    float rt = g_r[base];

    for (int t = 0; t < TLEN; t++) {
        size_t off = base + (size_t)t * HD;
        float ktn = 0.f, vtn = 0.f, rtn = 0.f;
        if (t + 1 < TLEN) {
            ktn = g_k[off + HD];
            vtn = g_v[off + HD];
            rtn = g_r[off + HD];
        }

        float mfo = fmaxf(mx, kt + tf);
        float e1  = __expf(mx - mfo);
        float e2  = __expf(kt + tf - mfo);
        float out = (e1 * num + e2 * vt) / (e1 * den + e2);

        float mfs = fmaxf(mx + td, kt);
        float e1s = __expf(mx + td - mfs);
        float e2s = __expf(kt - mfs);
        num = e1s * num + e2s * vt;
        den = e1s * den + e2s;
        mx  = mfs;

        g_ak[off] = __float2half_rn(out * rt);

        kt = ktn;
        vt = vtn;
        rt = rtn;
    }
}

// ---------------------------------------------------------------------------
// Launch
// ---------------------------------------------------------------------------
extern "C" void kernel_launch(void* const* d_in, const int* in_sizes, int n_in,
                              void* d_out, int out_size) {
    const float* hidden = (const float*)d_in[0];
    const float* time_decay = (const float*)d_in[1];
    const float* time_first = (const float*)d_in[2];
    const float* tmk = (const float*)d_in[3];
    const float* tmv = (const float*)d_in[4];
    const float* tmr = (const float*)d_in[5];
    const float* Wk = (const float*)d_in[6];
    const float* Wv = (const float*)d_in[7];
    const float* Wr = (const float*)d_in[8];
    const float* Wo = (const float*)d_in[9];

    __half *ak, *av, *ar, *wk, *wv, *wr, *wo;
    float *kb, *vb, *rb;
    cudaGetSymbolAddress((void**)&ak, g_ak);
    cudaGetSymbolAddress((void**)&av, g_av);
    cudaGetSymbolAddress((void**)&ar, g_ar);
    cudaGetSymbolAddress((void**)&wk, g_wk);
    cudaGetSymbolAddress((void**)&wv, g_wv);
    cudaGetSymbolAddress((void**)&wr, g_wr);
    cudaGetSymbolAddress((void**)&wo, g_wo);
    cudaGetSymbolAddress((void**)&kb, g_k);
    cudaGetSymbolAddress((void**)&vb, g_v);
    cudaGetSymbolAddress((void**)&rb, g_r);

    cudaFuncSetAttribute(gemm_f16<0>, cudaFuncAttributeMaxDynamicSharedMemorySize, SMEM_GEMM);
    cudaFuncSetAttribute(gemm_f16<1>, cudaFuncAttributeMaxDynamicSharedMemorySize, SMEM_GEMM);

    // 1. weight transposes (fp16)
    dim3 tgrid(HD / 32, HD / 32);
    transpose_half<<<tgrid, 256>>>(Wk, wk);
    transpose_half<<<tgrid, 256>>>(Wv, wv);
    transpose_half<<<tgrid, 256>>>(Wr, wr);
    transpose_half<<<tgrid, 256>>>(Wo, wo);

    // 2. mixes (fp16 planes)
    mix_kernel<<<(int)(TOT / 4 / 256), 256>>>(hidden, tmk, tmv, tmr);

    // 3. three input GEMMs (mma.sync fp16)
    dim3 grid(HD / BN, MROWS / BM);   // (16, 64)
    gemm_f16<0><<<grid, 256, SMEM_GEMM>>>(ak, wk, kb);
    gemm_f16<0><<<grid, 256, SMEM_GEMM>>>(av, wv, vb);
    gemm_f16<1><<<grid, 256, SMEM_GEMM>>>(ar, wr, rb);

    // 4. WKV scan (fused r*), writes p into g_ak
    wkv_kernel<<<128, 64>>>(time_decay, time_first);

    // 5. output GEMM
    gemm_f16<0><<<grid, 256, SMEM_GEMM>>>(ak, wo, (float*)d_out);
}

// round 7
// speedup vs baseline: 5.6667x; 1.9708x over previous
#include <cuda_runtime.h>
#include <cuda_fp16.h>
#include <cstdint>
#include <math.h>

// ---------------------------------------------------------------------------
// Problem dims (fixed)
// ---------------------------------------------------------------------------
constexpr int BATCH = 4;
constexpr int TLEN  = 2048;
constexpr int HD    = 2048;                  // N = K = 2048
constexpr int MROWS = BATCH * TLEN;          // 8192
constexpr size_t TOT = (size_t)MROWS * HD;   // 16,777,216
constexpr int CH    = BATCH * HD;            // 8192 scan channels
constexpr int SEG   = 8;
constexpr int SEGLEN = TLEN / SEG;           // 256

// GEMM tiling: CTA 128(M) x 256(N) x 64(K), 8 warps (2M x 4N), warp tile 64x64
constexpr int BM = 128;
constexpr int BN = 256;
constexpr int BK = 64;
constexpr int NITER = HD / BK;               // 32
constexpr int STAGES = 3;
constexpr int PITCH = 144;                   // 64 fp16 = 128B data + 16B pad
constexpr int A_PLANE = BM * PITCH;          // 18432
constexpr int B_PLANE = BN * PITCH;          // 36864
constexpr int STAGE_BYTES = A_PLANE + B_PLANE;   // 55296
constexpr int SMEM_GEMM = STAGES * STAGE_BYTES;  // 165888

// ---------------------------------------------------------------------------
// Scratch (device globals: allocation-free per harness rules)
// ---------------------------------------------------------------------------
__device__ __align__(256) __half g_ak[TOT];   // key-mix (reused as p = r*rwkv)
__device__ __align__(256) __half g_av[TOT];
__device__ __align__(256) __half g_ar[TOT];
__device__ __align__(256) float g_k[TOT];
__device__ __align__(256) float g_v[TOT];
__device__ __align__(256) float g_r[TOT];
// transposed weights: [N=2048, K=2048] fp16, K-major
__device__ __align__(256) __half g_wk[HD * HD];
__device__ __align__(256) __half g_wv[HD * HD];
__device__ __align__(256) __half g_wr[HD * HD];
__device__ __align__(256) __half g_wo[HD * HD];
// WKV segment summaries / prefixes: [SEG][CH]
__device__ float g_sn[SEG * CH];
__device__ float g_sd[SEG * CH];
__device__ float g_sm[SEG * CH];
__device__ float g_pn[SEG * CH];
__device__ float g_pd[SEG * CH];
__device__ float g_pm[SEG * CH];

// ---------------------------------------------------------------------------
// PTX helpers (base sm_103 target: cp.async, ldmatrix, mma.sync)
// ---------------------------------------------------------------------------
__device__ __forceinline__ uint32_t smem_u32(const void* p) {
    uint32_t a;
    asm("{ .reg .u64 t; cvta.to.shared.u64 t, %1; cvt.u32.u64 %0, t; }"
        : "=r"(a) : "l"(p));
    return a;
}

__device__ __forceinline__ void cp_async16(uint32_t s, const void* g) {
    asm volatile("cp.async.cg.shared.global [%0], [%1], 16;" :: "r"(s), "l"(g));
}
__device__ __forceinline__ void cp_commit() {
    asm volatile("cp.async.commit_group;" ::: "memory");
}
template <int N>
__device__ __forceinline__ void cp_wait() {
    asm volatile("cp.async.wait_group %0;" :: "n"(N) : "memory");
}

__device__ __forceinline__ void ldsm_x4(uint32_t* r, uint32_t addr) {
    asm volatile("ldmatrix.sync.aligned.m8n8.x4.shared.b16 {%0,%1,%2,%3}, [%4];"
        : "=r"(r[0]), "=r"(r[1]), "=r"(r[2]), "=r"(r[3]) : "r"(addr));
}

// mma.sync m16n8k16 fp16 -> fp32, D += A*B
__device__ __forceinline__ void mma16816(float* d, const uint32_t* a,
                                         uint32_t b0, uint32_t b1) {
    asm volatile(
        "mma.sync.aligned.m16n8k16.row.col.f32.f16.f16.f32 "
        "{%0,%1,%2,%3}, {%4,%5,%6,%7}, {%8,%9}, {%0,%1,%2,%3};"
        : "+f"(d[0]), "+f"(d[1]), "+f"(d[2]), "+f"(d[3])
        : "r"(a[0]), "r"(a[1]), "r"(a[2]), "r"(a[3]), "r"(b0), "r"(b1));
}

__device__ __forceinline__ uint32_t pack2h(__half a, __half b) {
    __half2 t(a, b);
    return *(uint32_t*)&t;
}

// ---------------------------------------------------------------------------
// Weight transpose:  W[K,N] fp32 -> T[N,K] fp16
// ---------------------------------------------------------------------------
__global__ void transpose_half(const float* __restrict__ W,
                               __half* __restrict__ T) {
    __shared__ float tile[32][33];
    int tx = threadIdx.x & 31;
    int ty0 = threadIdx.x >> 5;          // 0..7
    int bx = blockIdx.x * 32;            // n base
    int by = blockIdx.y * 32;            // k base
    #pragma unroll
    for (int i = 0; i < 32; i += 8)
        tile[ty0 + i][tx] = W[(size_t)(by + ty0 + i) * HD + bx + tx];
    __syncthreads();
    #pragma unroll
    for (int i = 0; i < 32; i += 8)
        T[(size_t)(bx + ty0 + i) * HD + by + tx] = __float2half_rn(tile[tx][ty0 + i]);
}

// ---------------------------------------------------------------------------
// Time-shift + three mixes -> three fp16 planes
// ---------------------------------------------------------------------------
__global__ void mix_kernel(const float* __restrict__ hidden,
                           const float* __restrict__ tmk,
                           const float* __restrict__ tmv,
                           const float* __restrict__ tmr) {
    int idx = blockIdx.x * blockDim.x + threadIdx.x;  // float4 index
    constexpr int HV = HD / 4;
    int row = idx / HV;
    int hv  = idx % HV;
    bool hasPrev = (row % TLEN) != 0;

    const float4* h4 = (const float4*)hidden;
    float4 cur  = h4[idx];
    float4 prev = hasPrev ? h4[idx - HV] : make_float4(0.f, 0.f, 0.f, 0.f);

    float4 mk = ((const float4*)tmk)[hv];
    float4 mv = ((const float4*)tmv)[hv];
    float4 mr = ((const float4*)tmr)[hv];

    float c[4] = {cur.x, cur.y, cur.z, cur.w};
    float p[4] = {prev.x, prev.y, prev.z, prev.w};
    float k_[4] = {mk.x, mk.y, mk.z, mk.w};
    float v_[4] = {mv.x, mv.y, mv.z, mv.w};
    float r_[4] = {mr.x, mr.y, mr.z, mr.w};

    __half hk[4], hv_[4], hr[4];
    #pragma unroll
    for (int i = 0; i < 4; i++) {
        hk[i]  = __float2half_rn(p[i] + k_[i] * (c[i] - p[i]));
        hv_[i] = __float2half_rn(p[i] + v_[i] * (c[i] - p[i]));
        hr[i]  = __float2half_rn(p[i] + r_[i] * (c[i] - p[i]));
    }

    uint2 out;
    out.x = pack2h(hk[0], hk[1]);  out.y = pack2h(hk[2], hk[3]);
    ((uint2*)g_ak)[idx] = out;
    out.x = pack2h(hv_[0], hv_[1]); out.y = pack2h(hv_[2], hv_[3]);
    ((uint2*)g_av)[idx] = out;
    out.x = pack2h(hr[0], hr[1]);  out.y = pack2h(hr[2], hr[3]);
    ((uint2*)g_ar)[idx] = out;
}

// ---------------------------------------------------------------------------
// fp16 mma.sync GEMM:  C[M,HD] = A[M,HD] @ Bt[HD,HD]^T  (Bt is [N,K] K-major)
// CTA 128x256x64, 8 warps (2M x 4N), warp tile 64x64, 3 stages.
// EPI: 0 = none, 1 = sigmoid.
// ---------------------------------------------------------------------------
template <int EPI>
__global__ void __launch_bounds__(256, 1)
gemm_f16(const __half* __restrict__ A,
         const __half* __restrict__ B,
         float* __restrict__ C) {
    extern __shared__ char smem[];
    uint32_t sbase = smem_u32(smem);
    int tid = threadIdx.x;
    int wid = tid >> 5;
    int lid = tid & 31;
    int mBase = blockIdx.y * BM;
    int nBase = blockIdx.x * BN;

    int wm = (wid & 1) * 64;       // warp M offset
    int wn = (wid >> 1) * 64;      // warp N offset

    // gmem->smem: A 1024 chunks(16B) + B 2048 chunks = 3072, 12/thread
    auto load_stage = [&](int buf, int k0) {
        uint32_t st = sbase + buf * STAGE_BYTES;
        #pragma unroll
        for (int i = 0; i < 4; i++) {
            int id = tid + i * 256;
            int r = id >> 3, c = id & 7;
            cp_async16(st + (uint32_t)(r * PITCH + c * 16),
                       A + (size_t)(mBase + r) * HD + k0 + c * 8);
        }
        #pragma unroll
        for (int i = 0; i < 8; i++) {
            int id = tid + i * 256;
            int r = id >> 3, c = id & 7;
            cp_async16(st + A_PLANE + (uint32_t)(r * PITCH + c * 16),
                       B + (size_t)(nBase + r) * HD + k0 + c * 8);
        }
    };

    float acc[4][8][4];
    #pragma unroll
    for (int a = 0; a < 4; a++)
        #pragma unroll
        for (int b = 0; b < 8; b++)
            #pragma unroll
            for (int c = 0; c < 4; c++) acc[a][b][c] = 0.f;

    load_stage(0, 0);
    cp_commit();
    load_stage(1, BK);
    cp_commit();

    // A ldmatrix lane address: rows m = wm + (lid&15), byte (lid>>4)*16
    uint32_t aLane = (uint32_t)((wm + (lid & 15)) * PITCH + (lid >> 4) * 16);
    // B ldmatrix lane address for fn-pair p:
    // groups: g0 rows n0-7 byte 0, g1 rows n8-15 byte 0, g2 rows n0-7 byte16, g3 rows n8-15 byte16
    uint32_t bLane = (uint32_t)((wn + (lid & 7) + ((lid >> 3) & 1) * 8) * PITCH
                                + (lid >> 4) * 16);

    for (int s = 0; s < NITER; s++) {
        cp_wait<STAGES - 2>();
        __syncthreads();

        if (s + STAGES - 1 < NITER) {
            load_stage((s + STAGES - 1) % STAGES, (s + STAGES - 1) * BK);
            cp_commit();
        }

        uint32_t st = sbase + (s % STAGES) * STAGE_BYTES;
        uint32_t aA = st + aLane;
        uint32_t bB = st + A_PLANE + bLane;

        #pragma unroll
        for (int ks = 0; ks < 4; ks++) {     // 4 x k16 per stage
            uint32_t ah[4][4], bb[4][4];
            #pragma unroll
            for (int fm = 0; fm < 4; fm++)
                ldsm_x4(ah[fm], aA + fm * (16 * PITCH) + ks * 32);
            #pragma unroll
            for (int p = 0; p < 4; p++)      // each covers fn = 2p, 2p+1
                ldsm_x4(bb[p], bB + p * (16 * PITCH) + ks * 32);
            #pragma unroll
            for (int fm = 0; fm < 4; fm++)
                #pragma unroll
                for (int p = 0; p < 4; p++) {
                    mma16816(acc[fm][2 * p],     ah[fm], bb[p][0], bb[p][2]);
                    mma16816(acc[fm][2 * p + 1], ah[fm], bb[p][1], bb[p][3]);
                }
        }
    }

    // epilogue
    int gid = lid >> 2, tig = lid & 3;
    #pragma unroll
    for (int fm = 0; fm < 4; fm++) {
        int row0 = mBase + wm + fm * 16 + gid;
        #pragma unroll
        for (int fn = 0; fn < 8; fn++) {
            int col = nBase + wn + fn * 8 + tig * 2;
            float2 v0 = make_float2(acc[fm][fn][0], acc[fm][fn][1]);
            float2 v1 = make_float2(acc[fm][fn][2], acc[fm][fn][3]);
            if (EPI == 1) {
                v0.x = 1.f / (1.f + __expf(-v0.x));
                v0.y = 1.f / (1.f + __expf(-v0.y));
                v1.x = 1.f / (1.f + __expf(-v1.x));
                v1.y = 1.f / (1.f + __expf(-v1.y));
            }
            *(float2*)(C + (size_t)row0 * HD + col) = v0;
            *(float2*)(C + (size_t)(row0 + 8) * HD + col) = v1;
        }
    }
}

// ---------------------------------------------------------------------------
// WKV 3-phase segmented scan. Channel ch = b*HD + d. idx = seg*CH + ch.
// Pass A: per-segment state summary from zero init.
// ---------------------------------------------------------------------------
__global__ void wkv_passA(const float* __restrict__ time_decay) {
    int idx = blockIdx.x * blockDim.x + threadIdx.x;   // 0..SEG*CH-1
    int d = idx % HD;
    int bc = idx / HD;
    int b = bc % BATCH;
    int seg = bc / BATCH;

    float td = -__expf(time_decay[d]);
    float num = 0.f, den = 0.f, mx = -1e38f;
    size_t base = (size_t)b * TLEN * HD + d;

    for (int t = seg * SEGLEN; t < (seg + 1) * SEGLEN; t++) {
        size_t off = base + (size_t)t * HD;
        float kt = g_k[off];
        float vt = g_v[off];
        float mfs = fmaxf(mx + td, kt);
        float e1s = __expf(mx + td - mfs);
        float e2s = __expf(kt - mfs);
        num = e1s * num + e2s * vt;
        den = e1s * den + e2s;
        mx  = mfs;
    }
    g_sn[idx] = num;
    g_sd[idx] = den;
    g_sm[idx] = mx;
}

// Pass B: stitch summaries -> incoming prefix state for each segment.
__global__ void wkv_passB(const float* __restrict__ time_decay) {
    int ch = blockIdx.x * blockDim.x + threadIdx.x;   // 0..CH-1
    int d = ch % HD;
    float td = -__expf(time_decay[d]);
    float decL = td * (float)SEGLEN;

    float n0 = 0.f, d0 = 0.f, m0 = -1e38f;
    #pragma unroll
    for (int s = 0; s < SEG; s++) {
        int o = s * CH + ch;
        g_pn[o] = n0;
        g_pd[o] = d0;
        g_pm[o] = m0;
        float ns = g_sn[o], ds = g_sd[o], ms = g_sm[o];
        float mA = m0 + decL;
        float mn = fmaxf(ms, mA);
        float ea = __expf(mA - mn);
        float eb = __expf(ms - mn);
        n0 = ea * n0 + eb * ns;
        d0 = ea * d0 + eb * ds;
        m0 = mn;
    }
}

// Pass C: rescan with correct incoming state, emit p = r * rwkv (fp16 into g_ak).
__global__ void wkv_passC(const float* __restrict__ time_decay,
                          const float* __restrict__ time_first) {
    int idx = blockIdx.x * blockDim.x + threadIdx.x;
    int d = idx % HD;
    int bc = idx / HD;
    int b = bc % BATCH;
    int seg = bc / BATCH;

    float td = -__expf(time_decay[d]);
    float tf = time_first[d];

    float num = g_pn[idx], den = g_pd[idx], mx = g_pm[idx];
    size_t base = (size_t)b * TLEN * HD + d;

    for (int t = seg * SEGLEN; t < (seg + 1) * SEGLEN; t++) {
        size_t off = base + (size_t)t * HD;
        float kt = g_k[off];
        float vt = g_v[off];
        float rt = g_r[off];

        float mfo = fmaxf(mx, kt + tf);
        float e1  = __expf(mx - mfo);
        float e2  = __expf(kt + tf - mfo);
        float out = (e1 * num + e2 * vt) / (e1 * den + e2);

        float mfs = fmaxf(mx + td, kt);
        float e1s = __expf(mx + td - mfs);
        float e2s = __expf(kt - mfs);
        num = e1s * num + e2s * vt;
        den = e1s * den + e2s;
        mx  = mfs;

        g_ak[off] = __float2half_rn(out * rt);
    }
}

// ---------------------------------------------------------------------------
// Launch
// ---------------------------------------------------------------------------
extern "C" void kernel_launch(void* const* d_in, const int* in_sizes, int n_in,
                              void* d_out, int out_size) {
    const float* hidden = (const float*)d_in[0];
    const float* time_decay = (const float*)d_in[1];
    const float* time_first = (const float*)d_in[2];
    const float* tmk = (const float*)d_in[3];
    const float* tmv = (const float*)d_in[4];
    const float* tmr = (const float*)d_in[5];
    const float* Wk = (const float*)d_in[6];
    const float* Wv = (const float*)d_in[7];
    const float* Wr = (const float*)d_in[8];
    const float* Wo = (const float*)d_in[9];

    __half *ak, *av, *ar, *wk, *wv, *wr, *wo;
    float *kb, *vb, *rb;
    cudaGetSymbolAddress((void**)&ak, g_ak);
    cudaGetSymbolAddress((void**)&av, g_av);
    cudaGetSymbolAddress((void**)&ar, g_ar);
    cudaGetSymbolAddress((void**)&wk, g_wk);
    cudaGetSymbolAddress((void**)&wv, g_wv);
    cudaGetSymbolAddress((void**)&wr, g_wr);
    cudaGetSymbolAddress((void**)&wo, g_wo);
    cudaGetSymbolAddress((void**)&kb, g_k);
    cudaGetSymbolAddress((void**)&vb, g_v);
    cudaGetSymbolAddress((void**)&rb, g_r);

    cudaFuncSetAttribute(gemm_f16<0>, cudaFuncAttributeMaxDynamicSharedMemorySize, SMEM_GEMM);
    cudaFuncSetAttribute(gemm_f16<1>, cudaFuncAttributeMaxDynamicSharedMemorySize, SMEM_GEMM);

    // 1. weight transposes (fp16)
    dim3 tgrid(HD / 32, HD / 32);
    transpose_half<<<tgrid, 256>>>(Wk, wk);
    transpose_half<<<tgrid, 256>>>(Wv, wv);
    transpose_half<<<tgrid, 256>>>(Wr, wr);
    transpose_half<<<tgrid, 256>>>(Wo, wo);

    // 2. mixes (fp16 planes)
    mix_kernel<<<(int)(TOT / 4 / 256), 256>>>(hidden, tmk, tmv, tmr);

    // 3. three input GEMMs
    dim3 grid(HD / BN, MROWS / BM);   // (8, 64)
    gemm_f16<0><<<grid, 256, SMEM_GEMM>>>(ak, wk, kb);
    gemm_f16<0><<<grid, 256, SMEM_GEMM>>>(av, wv, vb);
    gemm_f16<1><<<grid, 256, SMEM_GEMM>>>(ar, wr, rb);

    // 4. WKV segmented scan, writes p into g_ak
    wkv_passA<<<SEG * CH / 256, 256>>>(time_decay);
    wkv_passB<<<CH / 256, 256>>>(time_decay);
    wkv_passC<<<SEG * CH / 256, 256>>>(time_decay, time_first);

    // 5. output GEMM
    gemm_f16<0><<<grid, 256, SMEM_GEMM>>>(ak, wo, (float*)d_out);
}

// round 8
// speedup vs baseline: 6.5788x; 1.1609x over previous
#include <cuda_runtime.h>
#include <cuda_fp16.h>
#include <cstdint>
#include <math.h>

// ---------------------------------------------------------------------------
// Problem dims (fixed)
// ---------------------------------------------------------------------------
constexpr int BATCH = 4;
constexpr int TLEN  = 2048;
constexpr int HD    = 2048;                  // N = K = 2048
constexpr int MROWS = BATCH * TLEN;          // 8192
constexpr size_t TOT = (size_t)MROWS * HD;   // 16,777,216
constexpr int CH    = BATCH * HD;            // 8192 scan channels
constexpr int SEG   = 8;
constexpr int SEGLEN = TLEN / SEG;           // 256

// GEMM tiling: CTA 128x128x64, 8 warps (2M x 4N), warp tile 64x32, 3 stages,
// 2 CTAs/SM (smem 110.6 KB, regs <= 128)
constexpr int BM = 128;
constexpr int BN = 128;
constexpr int BK = 64;
constexpr int NITER = HD / BK;               // 32
constexpr int STAGES = 3;
constexpr int PITCH = 144;                   // 64 fp16 = 128B data + 16B pad
constexpr int PLANE = 128 * PITCH;           // 18432
constexpr int STAGE_BYTES = 2 * PLANE;       // A + B = 36864
constexpr int SMEM_GEMM = STAGES * STAGE_BYTES;  // 110592

// ---------------------------------------------------------------------------
// Scratch (device globals: allocation-free per harness rules)
// ---------------------------------------------------------------------------
__device__ __align__(256) __half g_ak[TOT];   // key-mix (reused as p = r*rwkv)
__device__ __align__(256) __half g_av[TOT];
__device__ __align__(256) __half g_ar[TOT];
__device__ __align__(256) float g_k[TOT];
__device__ __align__(256) float g_v[TOT];
__device__ __align__(256) float g_r[TOT];
// transposed weights: [N=2048, K=2048] fp16, K-major
__device__ __align__(256) __half g_wk[HD * HD];
__device__ __align__(256) __half g_wv[HD * HD];
__device__ __align__(256) __half g_wr[HD * HD];
__device__ __align__(256) __half g_wo[HD * HD];
// WKV segment summaries / prefixes: [SEG][CH]
__device__ float g_sn[SEG * CH];
__device__ float g_sd[SEG * CH];
__device__ float g_sm[SEG * CH];
__device__ float g_pn[SEG * CH];
__device__ float g_pd[SEG * CH];
__device__ float g_pm[SEG * CH];

// ---------------------------------------------------------------------------
// PTX helpers (base sm_103 target: cp.async, ldmatrix, mma.sync)
// ---------------------------------------------------------------------------
__device__ __forceinline__ uint32_t smem_u32(const void* p) {
    uint32_t a;
    asm("{ .reg .u64 t; cvta.to.shared.u64 t, %1; cvt.u32.u64 %0, t; }"
        : "=r"(a) : "l"(p));
    return a;
}

__device__ __forceinline__ void cp_async16(uint32_t s, const void* g) {
    asm volatile("cp.async.cg.shared.global [%0], [%1], 16;" :: "r"(s), "l"(g));
}
__device__ __forceinline__ void cp_commit() {
    asm volatile("cp.async.commit_group;" ::: "memory");
}
template <int N>
__device__ __forceinline__ void cp_wait() {
    asm volatile("cp.async.wait_group %0;" :: "n"(N) : "memory");
}

__device__ __forceinline__ void ldsm_x4(uint32_t* r, uint32_t addr) {
    asm volatile("ldmatrix.sync.aligned.m8n8.x4.shared.b16 {%0,%1,%2,%3}, [%4];"
        : "=r"(r[0]), "=r"(r[1]), "=r"(r[2]), "=r"(r[3]) : "r"(addr));
}

// mma.sync m16n8k16 fp16 -> fp32, D += A*B
__device__ __forceinline__ void mma16816(float* d, const uint32_t* a,
                                         uint32_t b0, uint32_t b1) {
    asm volatile(
        "mma.sync.aligned.m16n8k16.row.col.f32.f16.f16.f32 "
        "{%0,%1,%2,%3}, {%4,%5,%6,%7}, {%8,%9}, {%0,%1,%2,%3};"
        : "+f"(d[0]), "+f"(d[1]), "+f"(d[2]), "+f"(d[3])
        : "r"(a[0]), "r"(a[1]), "r"(a[2]), "r"(a[3]), "r"(b0), "r"(b1));
}

__device__ __forceinline__ uint32_t pack2h(__half a, __half b) {
    __half2 t(a, b);
    return *(uint32_t*)&t;
}

// ---------------------------------------------------------------------------
// Fused weight transposes:  W[K,N] fp32 -> T[N,K] fp16  (z selects matrix)
// ---------------------------------------------------------------------------
__global__ void transpose_half4(const float* __restrict__ W0,
                                const float* __restrict__ W1,
                                const float* __restrict__ W2,
                                const float* __restrict__ W3,
                                __half* __restrict__ T0,
                                __half* __restrict__ T1,
                                __half* __restrict__ T2,
                                __half* __restrict__ T3) {
    const float* W;
    __half* T;
    switch (blockIdx.z) {
        case 0: W = W0; T = T0; break;
        case 1: W = W1; T = T1; break;
        case 2: W = W2; T = T2; break;
        default: W = W3; T = T3; break;
    }
    __shared__ float tile[32][33];
    int tx = threadIdx.x & 31;
    int ty0 = threadIdx.x >> 5;          // 0..7
    int bx = blockIdx.x * 32;            // n base
    int by = blockIdx.y * 32;            // k base
    #pragma unroll
    for (int i = 0; i < 32; i += 8)
        tile[ty0 + i][tx] = W[(size_t)(by + ty0 + i) * HD + bx + tx];
    __syncthreads();
    #pragma unroll
    for (int i = 0; i < 32; i += 8)
        T[(size_t)(bx + ty0 + i) * HD + by + tx] = __float2half_rn(tile[tx][ty0 + i]);
}

// ---------------------------------------------------------------------------
// Time-shift + three mixes -> three fp16 planes
// ---------------------------------------------------------------------------
__global__ void mix_kernel(const float* __restrict__ hidden,
                           const float* __restrict__ tmk,
                           const float* __restrict__ tmv,
                           const float* __restrict__ tmr) {
    int idx = blockIdx.x * blockDim.x + threadIdx.x;  // float4 index
    constexpr int HV = HD / 4;
    int row = idx / HV;
    int hv  = idx % HV;
    bool hasPrev = (row % TLEN) != 0;

    const float4* h4 = (const float4*)hidden;
    float4 cur  = h4[idx];
    float4 prev = hasPrev ? h4[idx - HV] : make_float4(0.f, 0.f, 0.f, 0.f);

    float4 mk = ((const float4*)tmk)[hv];
    float4 mv = ((const float4*)tmv)[hv];
    float4 mr = ((const float4*)tmr)[hv];

    float c[4] = {cur.x, cur.y, cur.z, cur.w};
    float p[4] = {prev.x, prev.y, prev.z, prev.w};
    float k_[4] = {mk.x, mk.y, mk.z, mk.w};
    float v_[4] = {mv.x, mv.y, mv.z, mv.w};
    float r_[4] = {mr.x, mr.y, mr.z, mr.w};

    __half hk[4], hv_[4], hr[4];
    #pragma unroll
    for (int i = 0; i < 4; i++) {
        hk[i]  = __float2half_rn(p[i] + k_[i] * (c[i] - p[i]));
        hv_[i] = __float2half_rn(p[i] + v_[i] * (c[i] - p[i]));
        hr[i]  = __float2half_rn(p[i] + r_[i] * (c[i] - p[i]));
    }

    uint2 out;
    out.x = pack2h(hk[0], hk[1]);  out.y = pack2h(hk[2], hk[3]);
    ((uint2*)g_ak)[idx] = out;
    out.x = pack2h(hv_[0], hv_[1]); out.y = pack2h(hv_[2], hv_[3]);
    ((uint2*)g_av)[idx] = out;
    out.x = pack2h(hr[0], hr[1]);  out.y = pack2h(hr[2], hr[3]);
    ((uint2*)g_ar)[idx] = out;
}

// ---------------------------------------------------------------------------
// fp16 mma.sync GEMM:  C[M,HD] = A[M,HD] @ Bt[HD,HD]^T  (Bt is [N,K] K-major)
// CTA 128x128x64, 8 warps (2M x 4N), warp tile 64x32, 3 stages, 2 CTAs/SM.
// blockIdx.z selects the (A, B, C) triple; epi sigmoid when z == sigz.
// ---------------------------------------------------------------------------
__global__ void __launch_bounds__(256, 2)
gemm_f16(const __half* __restrict__ A0, const __half* __restrict__ A1,
         const __half* __restrict__ A2,
         const __half* __restrict__ B0, const __half* __restrict__ B1,
         const __half* __restrict__ B2,
         float* __restrict__ C0, float* __restrict__ C1, float* __restrict__ C2,
         int sigz) {
    extern __shared__ char smem[];
    uint32_t sbase = smem_u32(smem);

    const __half* A;
    const __half* B;
    float* C;
    int z = blockIdx.z;
    if (z == 0)      { A = A0; B = B0; C = C0; }
    else if (z == 1) { A = A1; B = B1; C = C1; }
    else             { A = A2; B = B2; C = C2; }
    bool sig = (z == sigz);

    int tid = threadIdx.x;
    int wid = tid >> 5;
    int lid = tid & 31;
    int mBase = blockIdx.y * BM;
    int nBase = blockIdx.x * BN;

    int wm = (wid & 1) * 64;       // warp M offset
    int wn = (wid >> 1) * 32;      // warp N offset

    // gmem->smem: A 1024 chunks(16B) + B 1024 chunks = 2048, 8/thread
    auto load_stage = [&](int buf, int k0) {
        uint32_t st = sbase + buf * STAGE_BYTES;
        #pragma unroll
        for (int i = 0; i < 4; i++) {
            int id = tid + i * 256;
            int r = id >> 3, c = id & 7;
            uint32_t so = (uint32_t)(r * PITCH + c * 16);
            cp_async16(st + so,         A + (size_t)(mBase + r) * HD + k0 + c * 8);
            cp_async16(st + PLANE + so, B + (size_t)(nBase + r) * HD + k0 + c * 8);
        }
    };

    float acc[4][4][4];
    #pragma unroll
    for (int a = 0; a < 4; a++)
        #pragma unroll
        for (int b = 0; b < 4; b++)
            #pragma unroll
            for (int c = 0; c < 4; c++) acc[a][b][c] = 0.f;

    load_stage(0, 0);
    cp_commit();
    load_stage(1, BK);
    cp_commit();

    // A ldmatrix lane address: rows m = wm + (lid&15), byte (lid>>4)*16
    uint32_t aLane = (uint32_t)((wm + (lid & 15)) * PITCH + (lid >> 4) * 16);
    // B ldmatrix lane address (pair p covers fn = 2p, 2p+1)
    uint32_t bLane = (uint32_t)((wn + (lid & 7) + ((lid >> 3) & 1) * 8) * PITCH
                                + (lid >> 4) * 16);

    for (int s = 0; s < NITER; s++) {
        cp_wait<STAGES - 2>();
        __syncthreads();

        if (s + STAGES - 1 < NITER) {
            load_stage((s + STAGES - 1) % STAGES, (s + STAGES - 1) * BK);
            cp_commit();
        }

        uint32_t st = sbase + (s % STAGES) * STAGE_BYTES;
        uint32_t aA = st + aLane;
        uint32_t bB = st + PLANE + bLane;

        #pragma unroll
        for (int ks = 0; ks < 4; ks++) {     // 4 x k16 per stage
            uint32_t ah[4][4], bb[2][4];
            #pragma unroll
            for (int fm = 0; fm < 4; fm++)
                ldsm_x4(ah[fm], aA + fm * (16 * PITCH) + ks * 32);
            #pragma unroll
            for (int p = 0; p < 2; p++)      // each covers fn = 2p, 2p+1
                ldsm_x4(bb[p], bB + p * (16 * PITCH) + ks * 32);
            #pragma unroll
            for (int fm = 0; fm < 4; fm++)
                #pragma unroll
                for (int p = 0; p < 2; p++) {
                    mma16816(acc[fm][2 * p],     ah[fm], bb[p][0], bb[p][2]);
                    mma16816(acc[fm][2 * p + 1], ah[fm], bb[p][1], bb[p][3]);
                }
        }
    }

    // epilogue
    int gid = lid >> 2, tig = lid & 3;
    #pragma unroll
    for (int fm = 0; fm < 4; fm++) {
        int row0 = mBase + wm + fm * 16 + gid;
        #pragma unroll
        for (int fn = 0; fn < 4; fn++) {
            int col = nBase + wn + fn * 8 + tig * 2;
            float2 v0 = make_float2(acc[fm][fn][0], acc[fm][fn][1]);
            float2 v1 = make_float2(acc[fm][fn][2], acc[fm][fn][3]);
            if (sig) {
                v0.x = 1.f / (1.f + __expf(-v0.x));
                v0.y = 1.f / (1.f + __expf(-v0.y));
                v1.x = 1.f / (1.f + __expf(-v1.x));
                v1.y = 1.f / (1.f + __expf(-v1.y));
            }
            *(float2*)(C + (size_t)row0 * HD + col) = v0;
            *(float2*)(C + (size_t)(row0 + 8) * HD + col) = v1;
        }
    }
}

// ---------------------------------------------------------------------------
// WKV 3-phase segmented scan. Channel ch = b*HD + d. idx = seg*CH + ch.
// ---------------------------------------------------------------------------
__global__ void wkv_passA(const float* __restrict__ time_decay) {
    int idx = blockIdx.x * blockDim.x + threadIdx.x;   // 0..SEG*CH-1
    int d = idx % HD;
    int bc = idx / HD;
    int b = bc % BATCH;
    int seg = bc / BATCH;

    float td = -__expf(time_decay[d]);
    float num = 0.f, den = 0.f, mx = -1e38f;
    size_t base = (size_t)b * TLEN * HD + d;

    for (int t = seg * SEGLEN; t < (seg + 1) * SEGLEN; t++) {
        size_t off = base + (size_t)t * HD;
        float kt = g_k[off];
        float vt = g_v[off];
        float mfs = fmaxf(mx + td, kt);
        float e1s = __expf(mx + td - mfs);
        float e2s = __expf(kt - mfs);
        num = e1s * num + e2s * vt;
        den = e1s * den + e2s;
        mx  = mfs;
    }
    g_sn[idx] = num;
    g_sd[idx] = den;
    g_sm[idx] = mx;
}

__global__ void wkv_passB(const float* __restrict__ time_decay) {
    int ch = blockIdx.x * blockDim.x + threadIdx.x;   // 0..CH-1
    int d = ch % HD;
    float td = -__expf(time_decay[d]);
    float decL = td * (float)SEGLEN;

    float n0 = 0.f, d0 = 0.f, m0 = -1e38f;
    #pragma unroll
    for (int s = 0; s < SEG; s++) {
        int o = s * CH + ch;
        g_pn[o] = n0;
        g_pd[o] = d0;
        g_pm[o] = m0;
        float ns = g_sn[o], ds = g_sd[o], ms = g_sm[o];
        float mA = m0 + decL;
        float mn = fmaxf(ms, mA);
        float ea = __expf(mA - mn);
        float eb = __expf(ms - mn);
        n0 = ea * n0 + eb * ns;
        d0 = ea * d0 + eb * ds;
        m0 = mn;
    }
}

__global__ void wkv_passC(const float* __restrict__ time_decay,
                          const float* __restrict__ time_first) {
    int idx = blockIdx.x * blockDim.x + threadIdx.x;
    int d = idx % HD;
    int bc = idx / HD;
    int b = bc % BATCH;
    int seg = bc / BATCH;

    float td = -__expf(time_decay[d]);
    float tf = time_first[d];

    float num = g_pn[idx], den = g_pd[idx], mx = g_pm[idx];
    size_t base = (size_t)b * TLEN * HD + d;

    for (int t = seg * SEGLEN; t < (seg + 1) * SEGLEN; t++) {
        size_t off = base + (size_t)t * HD;
        float kt = g_k[off];
        float vt = g_v[off];
        float rt = g_r[off];

        float mfo = fmaxf(mx, kt + tf);
        float e1  = __expf(mx - mfo);
        float e2  = __expf(kt + tf - mfo);
        float out = (e1 * num + e2 * vt) / (e1 * den + e2);

        float mfs = fmaxf(mx + td, kt);
        float e1s = __expf(mx + td - mfs);
        float e2s = __expf(kt - mfs);
        num = e1s * num + e2s * vt;
        den = e1s * den + e2s;
        mx  = mfs;

        g_ak[off] = __float2half_rn(out * rt);
    }
}

// ---------------------------------------------------------------------------
// Launch
// ---------------------------------------------------------------------------
extern "C" void kernel_launch(void* const* d_in, const int* in_sizes, int n_in,
                              void* d_out, int out_size) {
    const float* hidden = (const float*)d_in[0];
    const float* time_decay = (const float*)d_in[1];
    const float* time_first = (const float*)d_in[2];
    const float* tmk = (const float*)d_in[3];
    const float* tmv = (const float*)d_in[4];
    const float* tmr = (const float*)d_in[5];
    const float* Wk = (const float*)d_in[6];
    const float* Wv = (const float*)d_in[7];
    const float* Wr = (const float*)d_in[8];
    const float* Wo = (const float*)d_in[9];

    __half *ak, *av, *ar, *wk, *wv, *wr, *wo;
    float *kb, *vb, *rb;
    cudaGetSymbolAddress((void**)&ak, g_ak);
    cudaGetSymbolAddress((void**)&av, g_av);
    cudaGetSymbolAddress((void**)&ar, g_ar);
    cudaGetSymbolAddress((void**)&wk, g_wk);
    cudaGetSymbolAddress((void**)&wv, g_wv);
    cudaGetSymbolAddress((void**)&wr, g_wr);
    cudaGetSymbolAddress((void**)&wo, g_wo);
    cudaGetSymbolAddress((void**)&kb, g_k);
    cudaGetSymbolAddress((void**)&vb, g_v);
    cudaGetSymbolAddress((void**)&rb, g_r);

    cudaFuncSetAttribute(gemm_f16, cudaFuncAttributeMaxDynamicSharedMemorySize, SMEM_GEMM);

    // 1. weight transposes (fused, z = matrix index)
    transpose_half4<<<dim3(HD / 32, HD / 32, 4), 256>>>(Wk, Wv, Wr, Wo,
                                                        wk, wv, wr, wo);

    // 2. mixes (fp16 planes)
    mix_kernel<<<(int)(TOT / 4 / 256), 256>>>(hidden, tmk, tmv, tmr);

    // 3. three input GEMMs in ONE launch (z selects k/v/r; z==2 gets sigmoid)
    dim3 grid3(HD / BN, MROWS / BM, 3);   // (16, 64, 3)
    gemm_f16<<<grid3, 256, SMEM_GEMM>>>(ak, av, ar, wk, wv, wr, kb, vb, rb, 2);

    // 4. WKV segmented scan, writes p into g_ak
    wkv_passA<<<SEG * CH / 256, 256>>>(time_decay);
    wkv_passB<<<CH / 256, 256>>>(time_decay);
    wkv_passC<<<SEG * CH / 256, 256>>>(time_decay, time_first);

    // 5. output GEMM
    dim3 grid1(HD / BN, MROWS / BM, 1);
    gemm_f16<<<grid1, 256, SMEM_GEMM>>>(ak, ak, ak, wo, wo, wo,
                                        (float*)d_out, (float*)d_out,
                                        (float*)d_out, -1);
}

// round 9
// speedup vs baseline: 7.3331x; 1.1147x over previous
#include <cuda_runtime.h>
#include <cuda_fp16.h>
#include <cstdint>
#include <math.h>

// ---------------------------------------------------------------------------
// Problem dims (fixed)
// ---------------------------------------------------------------------------
constexpr int BATCH = 4;
constexpr int TLEN  = 2048;
constexpr int HD    = 2048;                  // N = K = 2048
constexpr int MROWS = BATCH * TLEN;          // 8192
constexpr size_t TOT = (size_t)MROWS * HD;   // 16,777,216
constexpr int CH    = BATCH * HD;            // 8192 scan channels
constexpr int SEG   = 32;
constexpr int SEGLEN = TLEN / SEG;           // 64

// GEMM tiling: CTA 128x128x64, 8 warps (2M x 4N), warp tile 64x32, 3 stages,
// 2 CTAs/SM (smem 110.6 KB, regs <= 128)
constexpr int BM = 128;
constexpr int BN = 128;
constexpr int BK = 64;
constexpr int NITER = HD / BK;               // 32
constexpr int STAGES = 3;
constexpr int PITCH = 144;                   // 64 fp16 = 128B data + 16B pad
constexpr int PLANE = 128 * PITCH;           // 18432
constexpr int STAGE_BYTES = 2 * PLANE;       // A + B = 36864
constexpr int SMEM_GEMM = STAGES * STAGE_BYTES;  // 110592

// ---------------------------------------------------------------------------
// Scratch (device globals: allocation-free per harness rules)
// ---------------------------------------------------------------------------
__device__ __align__(256) __half g_ak[TOT];   // key-mix (reused as p = r*rwkv)
__device__ __align__(256) __half g_av[TOT];
__device__ __align__(256) __half g_ar[TOT];
__device__ __align__(256) float g_k[TOT];
__device__ __align__(256) float g_v[TOT];
__device__ __align__(256) float g_r[TOT];
// transposed weights: [N=2048, K=2048] fp16, K-major
__device__ __align__(256) __half g_wk[HD * HD];
__device__ __align__(256) __half g_wv[HD * HD];
__device__ __align__(256) __half g_wr[HD * HD];
__device__ __align__(256) __half g_wo[HD * HD];
// WKV segment summaries / prefixes: [SEG][CH]
__device__ float g_sn[SEG * CH];
__device__ float g_sd[SEG * CH];
__device__ float g_sm[SEG * CH];
__device__ float g_pn[SEG * CH];
__device__ float g_pd[SEG * CH];
__device__ float g_pm[SEG * CH];

// ---------------------------------------------------------------------------
// PTX helpers (base sm_103 target: cp.async, ldmatrix, mma.sync)
// ---------------------------------------------------------------------------
__device__ __forceinline__ uint32_t smem_u32(const void* p) {
    uint32_t a;
    asm("{ .reg .u64 t; cvta.to.shared.u64 t, %1; cvt.u32.u64 %0, t; }"
        : "=r"(a) : "l"(p));
    return a;
}

__device__ __forceinline__ void cp_async16(uint32_t s, const void* g) {
    asm volatile("cp.async.cg.shared.global [%0], [%1], 16;" :: "r"(s), "l"(g));
}
__device__ __forceinline__ void cp_commit() {
    asm volatile("cp.async.commit_group;" ::: "memory");
}
template <int N>
__device__ __forceinline__ void cp_wait() {
    asm volatile("cp.async.wait_group %0;" :: "n"(N) : "memory");
}

__device__ __forceinline__ void ldsm_x4(uint32_t* r, uint32_t addr) {
    asm volatile("ldmatrix.sync.aligned.m8n8.x4.shared.b16 {%0,%1,%2,%3}, [%4];"
        : "=r"(r[0]), "=r"(r[1]), "=r"(r[2]), "=r"(r[3]) : "r"(addr));
}

// mma.sync m16n8k16 fp16 -> fp32, D += A*B
__device__ __forceinline__ void mma16816(float* d, const uint32_t* a,
                                         uint32_t b0, uint32_t b1) {
    asm volatile(
        "mma.sync.aligned.m16n8k16.row.col.f32.f16.f16.f32 "
        "{%0,%1,%2,%3}, {%4,%5,%6,%7}, {%8,%9}, {%0,%1,%2,%3};"
        : "+f"(d[0]), "+f"(d[1]), "+f"(d[2]), "+f"(d[3])
        : "r"(a[0]), "r"(a[1]), "r"(a[2]), "r"(a[3]), "r"(b0), "r"(b1));
}

__device__ __forceinline__ uint32_t pack2h(__half a, __half b) {
    __half2 t(a, b);
    return *(uint32_t*)&t;
}

// ---------------------------------------------------------------------------
// Fused weight transposes:  W[K,N] fp32 -> T[N,K] fp16  (z selects matrix)
// ---------------------------------------------------------------------------
__global__ void transpose_half4(const float* __restrict__ W0,
                                const float* __restrict__ W1,
                                const float* __restrict__ W2,
                                const float* __restrict__ W3,
                                __half* __restrict__ T0,
                                __half* __restrict__ T1,
                                __half* __restrict__ T2,
                                __half* __restrict__ T3) {
    const float* W;
    __half* T;
    switch (blockIdx.z) {
        case 0: W = W0; T = T0; break;
        case 1: W = W1; T = T1; break;
        case 2: W = W2; T = T2; break;
        default: W = W3; T = T3; break;
    }
    __shared__ float tile[32][33];
    int tx = threadIdx.x & 31;
    int ty0 = threadIdx.x >> 5;          // 0..7
    int bx = blockIdx.x * 32;            // n base
    int by = blockIdx.y * 32;            // k base
    #pragma unroll
    for (int i = 0; i < 32; i += 8)
        tile[ty0 + i][tx] = W[(size_t)(by + ty0 + i) * HD + bx + tx];
    __syncthreads();
    #pragma unroll
    for (int i = 0; i < 32; i += 8)
        T[(size_t)(bx + ty0 + i) * HD + by + tx] = __float2half_rn(tile[tx][ty0 + i]);
}

// ---------------------------------------------------------------------------
// Time-shift + three mixes -> three fp16 planes
// ---------------------------------------------------------------------------
__global__ void mix_kernel(const float* __restrict__ hidden,
                           const float* __restrict__ tmk,
                           const float* __restrict__ tmv,
                           const float* __restrict__ tmr) {
    int idx = blockIdx.x * blockDim.x + threadIdx.x;  // float4 index
    constexpr int HV = HD / 4;
    int row = idx / HV;
    int hv  = idx % HV;
    bool hasPrev = (row % TLEN) != 0;

    const float4* h4 = (const float4*)hidden;
    float4 cur  = h4[idx];
    float4 prev = hasPrev ? h4[idx - HV] : make_float4(0.f, 0.f, 0.f, 0.f);

    float4 mk = ((const float4*)tmk)[hv];
    float4 mv = ((const float4*)tmv)[hv];
    float4 mr = ((const float4*)tmr)[hv];

    float c[4] = {cur.x, cur.y, cur.z, cur.w};
    float p[4] = {prev.x, prev.y, prev.z, prev.w};
    float k_[4] = {mk.x, mk.y, mk.z, mk.w};
    float v_[4] = {mv.x, mv.y, mv.z, mv.w};
    float r_[4] = {mr.x, mr.y, mr.z, mr.w};

    __half hk[4], hv_[4], hr[4];
    #pragma unroll
    for (int i = 0; i < 4; i++) {
        hk[i]  = __float2half_rn(p[i] + k_[i] * (c[i] - p[i]));
        hv_[i] = __float2half_rn(p[i] + v_[i] * (c[i] - p[i]));
        hr[i]  = __float2half_rn(p[i] + r_[i] * (c[i] - p[i]));
    }

    uint2 out;
    out.x = pack2h(hk[0], hk[1]);  out.y = pack2h(hk[2], hk[3]);
    ((uint2*)g_ak)[idx] = out;
    out.x = pack2h(hv_[0], hv_[1]); out.y = pack2h(hv_[2], hv_[3]);
    ((uint2*)g_av)[idx] = out;
    out.x = pack2h(hr[0], hr[1]);  out.y = pack2h(hr[2], hr[3]);
    ((uint2*)g_ar)[idx] = out;
}

// ---------------------------------------------------------------------------
// fp16 mma.sync GEMM:  C[M,HD] = A[M,HD] @ Bt[HD,HD]^T  (Bt is [N,K] K-major)
// CTA 128x128x64, 8 warps (2M x 4N), warp tile 64x32, 3 stages, 2 CTAs/SM.
// blockIdx.z selects the (A, B, C) triple; epi sigmoid when z == sigz.
// ---------------------------------------------------------------------------
__global__ void __launch_bounds__(256, 2)
gemm_f16(const __half* __restrict__ A0, const __half* __restrict__ A1,
         const __half* __restrict__ A2,
         const __half* __restrict__ B0, const __half* __restrict__ B1,
         const __half* __restrict__ B2,
         float* __restrict__ C0, float* __restrict__ C1, float* __restrict__ C2,
         int sigz) {
    extern __shared__ char smem[];
    uint32_t sbase = smem_u32(smem);

    const __half* A;
    const __half* B;
    float* C;
    int z = blockIdx.z;
    if (z == 0)      { A = A0; B = B0; C = C0; }
    else if (z == 1) { A = A1; B = B1; C = C1; }
    else             { A = A2; B = B2; C = C2; }
    bool sig = (z == sigz);

    int tid = threadIdx.x;
    int wid = tid >> 5;
    int lid = tid & 31;
    int mBase = blockIdx.y * BM;
    int nBase = blockIdx.x * BN;

    int wm = (wid & 1) * 64;       // warp M offset
    int wn = (wid >> 1) * 32;      // warp N offset

    // gmem->smem: A 1024 chunks(16B) + B 1024 chunks = 2048, 8/thread
    auto load_stage = [&](int buf, int k0) {
        uint32_t st = sbase + buf * STAGE_BYTES;
        #pragma unroll
        for (int i = 0; i < 4; i++) {
            int id = tid + i * 256;
            int r = id >> 3, c = id & 7;
            uint32_t so = (uint32_t)(r * PITCH + c * 16);
            cp_async16(st + so,         A + (size_t)(mBase + r) * HD + k0 + c * 8);
            cp_async16(st + PLANE + so, B + (size_t)(nBase + r) * HD + k0 + c * 8);
        }
    };

    float acc[4][4][4];
    #pragma unroll
    for (int a = 0; a < 4; a++)
        #pragma unroll
        for (int b = 0; b < 4; b++)
            #pragma unroll
            for (int c = 0; c < 4; c++) acc[a][b][c] = 0.f;

    load_stage(0, 0);
    cp_commit();
    load_stage(1, BK);
    cp_commit();

    // A ldmatrix lane address: rows m = wm + (lid&15), byte (lid>>4)*16
    uint32_t aLane = (uint32_t)((wm + (lid & 15)) * PITCH + (lid >> 4) * 16);
    // B ldmatrix lane address (pair p covers fn = 2p, 2p+1)
    uint32_t bLane = (uint32_t)((wn + (lid & 7) + ((lid >> 3) & 1) * 8) * PITCH
                                + (lid >> 4) * 16);

    for (int s = 0; s < NITER; s++) {
        cp_wait<STAGES - 2>();
        __syncthreads();

        if (s + STAGES - 1 < NITER) {
            load_stage((s + STAGES - 1) % STAGES, (s + STAGES - 1) * BK);
            cp_commit();
        }

        uint32_t st = sbase + (s % STAGES) * STAGE_BYTES;
        uint32_t aA = st + aLane;
        uint32_t bB = st + PLANE + bLane;

        #pragma unroll
        for (int ks = 0; ks < 4; ks++) {     // 4 x k16 per stage
            uint32_t ah[4][4], bb[2][4];
            #pragma unroll
            for (int fm = 0; fm < 4; fm++)
                ldsm_x4(ah[fm], aA + fm * (16 * PITCH) + ks * 32);
            #pragma unroll
            for (int p = 0; p < 2; p++)      // each covers fn = 2p, 2p+1
                ldsm_x4(bb[p], bB + p * (16 * PITCH) + ks * 32);
            #pragma unroll
            for (int fm = 0; fm < 4; fm++)
                #pragma unroll
                for (int p = 0; p < 2; p++) {
                    mma16816(acc[fm][2 * p],     ah[fm], bb[p][0], bb[p][2]);
                    mma16816(acc[fm][2 * p + 1], ah[fm], bb[p][1], bb[p][3]);
                }
        }
    }

    // epilogue
    int gid = lid >> 2, tig = lid & 3;
    #pragma unroll
    for (int fm = 0; fm < 4; fm++) {
        int row0 = mBase + wm + fm * 16 + gid;
        #pragma unroll
        for (int fn = 0; fn < 4; fn++) {
            int col = nBase + wn + fn * 8 + tig * 2;
            float2 v0 = make_float2(acc[fm][fn][0], acc[fm][fn][1]);
            float2 v1 = make_float2(acc[fm][fn][2], acc[fm][fn][3]);
            if (sig) {
                v0.x = 1.f / (1.f + __expf(-v0.x));
                v0.y = 1.f / (1.f + __expf(-v0.y));
                v1.x = 1.f / (1.f + __expf(-v1.x));
                v1.y = 1.f / (1.f + __expf(-v1.y));
            }
            *(float2*)(C + (size_t)row0 * HD + col) = v0;
            *(float2*)(C + (size_t)(row0 + 8) * HD + col) = v1;
        }
    }
}

// ---------------------------------------------------------------------------
// WKV 3-phase segmented scan. Channel ch = b*HD + d. idx = seg*CH + ch.
// SEG=32 segments of 64 steps: 262144 threads => latency fully hidden.
// ---------------------------------------------------------------------------
__global__ void wkv_passA(const float* __restrict__ time_decay) {
    int idx = blockIdx.x * blockDim.x + threadIdx.x;   // 0..SEG*CH-1
    int d = idx % HD;
    int bc = idx / HD;
    int b = bc % BATCH;
    int seg = bc / BATCH;

    float td = -__expf(time_decay[d]);
    float num = 0.f, den = 0.f, mx = -1e38f;
    size_t base = (size_t)b * TLEN * HD + d;

    for (int t = seg * SEGLEN; t < (seg + 1) * SEGLEN; t++) {
        size_t off = base + (size_t)t * HD;
        float kt = g_k[off];
        float vt = g_v[off];
        float mfs = fmaxf(mx + td, kt);
        float e1s = __expf(mx + td - mfs);
        float e2s = __expf(kt - mfs);
        num = e1s * num + e2s * vt;
        den = e1s * den + e2s;
        mx  = mfs;
    }
    g_sn[idx] = num;
    g_sd[idx] = den;
    g_sm[idx] = mx;
}

__global__ void wkv_passB(const float* __restrict__ time_decay) {
    int ch = blockIdx.x * blockDim.x + threadIdx.x;   // 0..CH-1
    int d = ch % HD;
    float td = -__expf(time_decay[d]);
    float decL = td * (float)SEGLEN;

    float n0 = 0.f, d0 = 0.f, m0 = -1e38f;
    #pragma unroll
    for (int s = 0; s < SEG; s++) {
        int o = s * CH + ch;
        g_pn[o] = n0;
        g_pd[o] = d0;
        g_pm[o] = m0;
        float ns = g_sn[o], ds = g_sd[o], ms = g_sm[o];
        float mA = m0 + decL;
        float mn = fmaxf(ms, mA);
        float ea = __expf(mA - mn);
        float eb = __expf(ms - mn);
        n0 = ea * n0 + eb * ns;
        d0 = ea * d0 + eb * ds;
        m0 = mn;
    }
}

__global__ void wkv_passC(const float* __restrict__ time_decay,
                          const float* __restrict__ time_first) {
    int idx = blockIdx.x * blockDim.x + threadIdx.x;
    int d = idx % HD;
    int bc = idx / HD;
    int b = bc % BATCH;
    int seg = bc / BATCH;

    float td = -__expf(time_decay[d]);
    float tf = time_first[d];

    float num = g_pn[idx], den = g_pd[idx], mx = g_pm[idx];
    size_t base = (size_t)b * TLEN * HD + d;

    for (int t = seg * SEGLEN; t < (seg + 1) * SEGLEN; t++) {
        size_t off = base + (size_t)t * HD;
        float kt = g_k[off];
        float vt = g_v[off];
        float rt = g_r[off];

        float mfo = fmaxf(mx, kt + tf);
        float e1  = __expf(mx - mfo);
        float e2  = __expf(kt + tf - mfo);
        float out = (e1 * num + e2 * vt) / (e1 * den + e2);

        float mfs = fmaxf(mx + td, kt);
        float e1s = __expf(mx + td - mfs);
        float e2s = __expf(kt - mfs);
        num = e1s * num + e2s * vt;
        den = e1s * den + e2s;
        mx  = mfs;

        g_ak[off] = __float2half_rn(out * rt);
    }
}

// ---------------------------------------------------------------------------
// Launch
// ---------------------------------------------------------------------------
extern "C" void kernel_launch(void* const* d_in, const int* in_sizes, int n_in,
                              void* d_out, int out_size) {
    const float* hidden = (const float*)d_in[0];
    const float* time_decay = (const float*)d_in[1];
    const float* time_first = (const float*)d_in[2];
    const float* tmk = (const float*)d_in[3];
    const float* tmv = (const float*)d_in[4];
    const float* tmr = (const float*)d_in[5];
    const float* Wk = (const float*)d_in[6];
    const float* Wv = (const float*)d_in[7];
    const float* Wr = (const float*)d_in[8];
    const float* Wo = (const float*)d_in[9];

    __half *ak, *av, *ar, *wk, *wv, *wr, *wo;
    float *kb, *vb, *rb;
    cudaGetSymbolAddress((void**)&ak, g_ak);
    cudaGetSymbolAddress((void**)&av, g_av);
    cudaGetSymbolAddress((void**)&ar, g_ar);
    cudaGetSymbolAddress((void**)&wk, g_wk);
    cudaGetSymbolAddress((void**)&wv, g_wv);
    cudaGetSymbolAddress((void**)&wr, g_wr);
    cudaGetSymbolAddress((void**)&wo, g_wo);
    cudaGetSymbolAddress((void**)&kb, g_k);
    cudaGetSymbolAddress((void**)&vb, g_v);
    cudaGetSymbolAddress((void**)&rb, g_r);

    cudaFuncSetAttribute(gemm_f16, cudaFuncAttributeMaxDynamicSharedMemorySize, SMEM_GEMM);

    // 1. weight transposes (fused, z = matrix index)
    transpose_half4<<<dim3(HD / 32, HD / 32, 4), 256>>>(Wk, Wv, Wr, Wo,
                                                        wk, wv, wr, wo);

    // 2. mixes (fp16 planes)
    mix_kernel<<<(int)(TOT / 4 / 256), 256>>>(hidden, tmk, tmv, tmr);

    // 3. three input GEMMs in ONE launch (z selects k/v/r; z==2 gets sigmoid)
    dim3 grid3(HD / BN, MROWS / BM, 3);   // (16, 64, 3)
    gemm_f16<<<grid3, 256, SMEM_GEMM>>>(ak, av, ar, wk, wv, wr, kb, vb, rb, 2);

    // 4. WKV segmented scan (SEG=32), writes p into g_ak
    wkv_passA<<<SEG * CH / 256, 256>>>(time_decay);
    wkv_passB<<<CH / 256, 256>>>(time_decay);
    wkv_passC<<<SEG * CH / 256, 256>>>(time_decay, time_first);

    // 5. output GEMM
    dim3 grid1(HD / BN, MROWS / BM, 1);
    gemm_f16<<<grid1, 256, SMEM_GEMM>>>(ak, ak, ak, wo, wo, wo,
                                        (float*)d_out, (float*)d_out,
                                        (float*)d_out, -1);
}

// round 11
// speedup vs baseline: 7.3387x; 1.0008x over previous
#include <cuda_runtime.h>
#include <cuda_fp16.h>
#include <cstdint>
#include <math.h>

// ---------------------------------------------------------------------------
// Problem dims (fixed)
// ---------------------------------------------------------------------------
constexpr int BATCH = 4;
constexpr int TLEN  = 2048;
constexpr int HD    = 2048;                  // N = K = 2048
constexpr int MROWS = BATCH * TLEN;          // 8192
constexpr size_t TOT = (size_t)MROWS * HD;   // 16,777,216
constexpr int CH    = BATCH * HD;            // 8192 scan channels
constexpr int SEG   = 32;
constexpr int SEGLEN = TLEN / SEG;           // 64

// GEMM tiling: CTA 128x128x64, 8 warps (2M x 4N), warp tile 64x32, 3 stages,
// 2 CTAs/SM (smem 110.6 KB, regs <= 128)
constexpr int BM = 128;
constexpr int BN = 128;
constexpr int BK = 64;
constexpr int NITER = HD / BK;               // 32
constexpr int STAGES = 3;
constexpr int PITCH = 144;                   // 64 fp16 = 128B data + 16B pad
constexpr int PLANE = 128 * PITCH;           // 18432
constexpr int STAGE_BYTES = 2 * PLANE;       // A + B = 36864
constexpr int SMEM_GEMM = STAGES * STAGE_BYTES;  // 110592

// ---------------------------------------------------------------------------
// Scratch (device globals: allocation-free per harness rules)
// ---------------------------------------------------------------------------
__device__ __align__(256) __half g_ak[TOT];   // key-mix (reused as p = r*rwkv)
__device__ __align__(256) __half g_av[TOT];
__device__ __align__(256) __half g_ar[TOT];
__device__ __align__(256) float g_k[TOT];
__device__ __align__(256) float g_v[TOT];
__device__ __align__(256) float g_r[TOT];
// transposed weights: [N=2048, K=2048] fp16, K-major
__device__ __align__(256) __half g_wk[HD * HD];
__device__ __align__(256) __half g_wv[HD * HD];
__device__ __align__(256) __half g_wr[HD * HD];
__device__ __align__(256) __half g_wo[HD * HD];
// WKV segment summaries / prefixes: [SEG][CH]
__device__ float g_sn[SEG * CH];
__device__ float g_sd[SEG * CH];
__device__ float g_sm[SEG * CH];
__device__ float g_pn[SEG * CH];
__device__ float g_pd[SEG * CH];
__device__ float g_pm[SEG * CH];

// ---------------------------------------------------------------------------
// PTX helpers (base sm_103 target: cp.async, ldmatrix, mma.sync)
// ---------------------------------------------------------------------------
__device__ __forceinline__ uint32_t smem_u32(const void* p) {
    uint32_t a;
    asm("{ .reg .u64 t; cvta.to.shared.u64 t, %1; cvt.u32.u64 %0, t; }"
        : "=r"(a) : "l"(p));
    return a;
}

__device__ __forceinline__ void cp_async16(uint32_t s, const void* g) {
    asm volatile("cp.async.cg.shared.global [%0], [%1], 16;" :: "r"(s), "l"(g));
}
__device__ __forceinline__ void cp_commit() {
    asm volatile("cp.async.commit_group;" ::: "memory");
}
template <int N>
__device__ __forceinline__ void cp_wait() {
    asm volatile("cp.async.wait_group %0;" :: "n"(N) : "memory");
}

__device__ __forceinline__ void ldsm_x4(uint32_t* r, uint32_t addr) {
    asm volatile("ldmatrix.sync.aligned.m8n8.x4.shared.b16 {%0,%1,%2,%3}, [%4];"
        : "=r"(r[0]), "=r"(r[1]), "=r"(r[2]), "=r"(r[3]) : "r"(addr));
}

// mma.sync m16n8k16 fp16 -> fp32, D += A*B
__device__ __forceinline__ void mma16816(float* d, const uint32_t* a,
                                         uint32_t b0, uint32_t b1) {
    asm volatile(
        "mma.sync.aligned.m16n8k16.row.col.f32.f16.f16.f32 "
        "{%0,%1,%2,%3}, {%4,%5,%6,%7}, {%8,%9}, {%0,%1,%2,%3};"
        : "+f"(d[0]), "+f"(d[1]), "+f"(d[2]), "+f"(d[3])
        : "r"(a[0]), "r"(a[1]), "r"(a[2]), "r"(a[3]), "r"(b0), "r"(b1));
}

__device__ __forceinline__ uint32_t pack2h(__half a, __half b) {
    __half2 t(a, b);
    return *(uint32_t*)&t;
}

// ---------------------------------------------------------------------------
// Fused weight transposes:  W[K,N] fp32 -> T[N,K] fp16  (z selects matrix)
// ---------------------------------------------------------------------------
__global__ void transpose_half4(const float* __restrict__ W0,
                                const float* __restrict__ W1,
                                const float* __restrict__ W2,
                                const float* __restrict__ W3,
                                __half* __restrict__ T0,
                                __half* __restrict__ T1,
                                __half* __restrict__ T2,
                                __half* __restrict__ T3) {
    const float* W;
    __half* T;
    switch (blockIdx.z) {
        case 0: W = W0; T = T0; break;
        case 1: W = W1; T = T1; break;
        case 2: W = W2; T = T2; break;
        default: W = W3; T = T3; break;
    }
    __shared__ float tile[32][33];
    int tx = threadIdx.x & 31;
    int ty0 = threadIdx.x >> 5;          // 0..7
    int bx = blockIdx.x * 32;            // n base
    int by = blockIdx.y * 32;            // k base
    #pragma unroll
    for (int i = 0; i < 32; i += 8)
        tile[ty0 + i][tx] = W[(size_t)(by + ty0 + i) * HD + bx + tx];
    __syncthreads();
    #pragma unroll
    for (int i = 0; i < 32; i += 8)
        T[(size_t)(bx + ty0 + i) * HD + by + tx] = __float2half_rn(tile[tx][ty0 + i]);
}

// ---------------------------------------------------------------------------
// Time-shift + three mixes -> three fp16 planes
// ---------------------------------------------------------------------------
__global__ void mix_kernel(const float* __restrict__ hidden,
                           const float* __restrict__ tmk,
                           const float* __restrict__ tmv,
                           const float* __restrict__ tmr) {
    int idx = blockIdx.x * blockDim.x + threadIdx.x;  // float4 index
    constexpr int HV = HD / 4;
    int row = idx / HV;
    int hv  = idx % HV;
    bool hasPrev = (row % TLEN) != 0;

    const float4* h4 = (const float4*)hidden;
    float4 cur  = h4[idx];
    float4 prev = hasPrev ? h4[idx - HV] : make_float4(0.f, 0.f, 0.f, 0.f);

    float4 mk = ((const float4*)tmk)[hv];
    float4 mv = ((const float4*)tmv)[hv];
    float4 mr = ((const float4*)tmr)[hv];

    float c[4] = {cur.x, cur.y, cur.z, cur.w};
    float p[4] = {prev.x, prev.y, prev.z, prev.w};
    float k_[4] = {mk.x, mk.y, mk.z, mk.w};
    float v_[4] = {mv.x, mv.y, mv.z, mv.w};
    float r_[4] = {mr.x, mr.y, mr.z, mr.w};

    __half hk[4], hv_[4], hr[4];
    #pragma unroll
    for (int i = 0; i < 4; i++) {
        hk[i]  = __float2half_rn(p[i] + k_[i] * (c[i] - p[i]));
        hv_[i] = __float2half_rn(p[i] + v_[i] * (c[i] - p[i]));
        hr[i]  = __float2half_rn(p[i] + r_[i] * (c[i] - p[i]));
    }

    uint2 out;
    out.x = pack2h(hk[0], hk[1]);  out.y = pack2h(hk[2], hk[3]);
    ((uint2*)g_ak)[idx] = out;
    out.x = pack2h(hv_[0], hv_[1]); out.y = pack2h(hv_[2], hv_[3]);
    ((uint2*)g_av)[idx] = out;
    out.x = pack2h(hr[0], hr[1]);  out.y = pack2h(hr[2], hr[3]);
    ((uint2*)g_ar)[idx] = out;
}

// ---------------------------------------------------------------------------
// fp16 mma.sync GEMM:  C[M,HD] = A[M,HD] @ Bt[HD,HD]^T  (Bt is [N,K] K-major)
// CTA 128x128x64, 8 warps (2M x 4N), warp tile 64x32, 3 stages, 2 CTAs/SM.
// Software-pipelined A fragments (double buffer across k16 steps).
// blockIdx.z selects the (A, B, C) triple; epi sigmoid when z == sigz.
// ---------------------------------------------------------------------------
__global__ void __launch_bounds__(256, 2)
gemm_f16(const __half* __restrict__ A0, const __half* __restrict__ A1,
         const __half* __restrict__ A2,
         const __half* __restrict__ B0, const __half* __restrict__ B1,
         const __half* __restrict__ B2,
         float* __restrict__ C0, float* __restrict__ C1, float* __restrict__ C2,
         int sigz) {
    extern __shared__ char smem[];
    uint32_t sbase = smem_u32(smem);

    const __half* A;
    const __half* B;
    float* C;
    int z = blockIdx.z;
    if (z == 0)      { A = A0; B = B0; C = C0; }
    else if (z == 1) { A = A1; B = B1; C = C1; }
    else             { A = A2; B = B2; C = C2; }
    bool sig = (z == sigz);

    int tid = threadIdx.x;
    int wid = tid >> 5;
    int lid = tid & 31;
    int mBase = blockIdx.y * BM;
    int nBase = blockIdx.x * BN;

    int wm = (wid & 1) * 64;       // warp M offset
    int wn = (wid >> 1) * 32;      // warp N offset

    // gmem->smem: A 1024 chunks(16B) + B 1024 chunks = 2048, 8/thread
    auto load_stage = [&](int buf, int k0) {
        uint32_t st = sbase + buf * STAGE_BYTES;
        #pragma unroll
        for (int i = 0; i < 4; i++) {
            int id = tid + i * 256;
            int r = id >> 3, c = id & 7;
            uint32_t so = (uint32_t)(r * PITCH + c * 16);
            cp_async16(st + so,         A + (size_t)(mBase + r) * HD + k0 + c * 8);
            cp_async16(st + PLANE + so, B + (size_t)(nBase + r) * HD + k0 + c * 8);
        }
    };

    float acc[4][4][4];
    #pragma unroll
    for (int a = 0; a < 4; a++)
        #pragma unroll
        for (int b = 0; b < 4; b++)
            #pragma unroll
            for (int c = 0; c < 4; c++) acc[a][b][c] = 0.f;

    load_stage(0, 0);
    cp_commit();
    load_stage(1, BK);
    cp_commit();

    // A ldmatrix lane address: rows m = wm + (lid&15), byte (lid>>4)*16
    uint32_t aLane = (uint32_t)((wm + (lid & 15)) * PITCH + (lid >> 4) * 16);
    // B ldmatrix lane address (pair p covers fn = 2p, 2p+1)
    uint32_t bLane = (uint32_t)((wn + (lid & 7) + ((lid >> 3) & 1) * 8) * PITCH
                                + (lid >> 4) * 16);

    uint32_t ah[2][4][4];   // double-buffered A frags

    for (int s = 0; s < NITER; s++) {
        cp_wait<STAGES - 2>();
        __syncthreads();

        if (s + STAGES - 1 < NITER) {
            load_stage((s + STAGES - 1) % STAGES, (s + STAGES - 1) * BK);
            cp_commit();
        }

        uint32_t st = sbase + (s % STAGES) * STAGE_BYTES;
        uint32_t aA = st + aLane;
        uint32_t bB = st + PLANE + bLane;

        // preload A frags for ks = 0
        #pragma unroll
        for (int fm = 0; fm < 4; fm++)
            ldsm_x4(ah[0][fm], aA + fm * (16 * PITCH));

        #pragma unroll
        for (int ks = 0; ks < 4; ks++) {     // 4 x k16 per stage
            int cur = ks & 1, nxt = cur ^ 1;
            uint32_t bb[2][4];
            #pragma unroll
            for (int p = 0; p < 2; p++)      // each covers fn = 2p, 2p+1
                ldsm_x4(bb[p], bB + p * (16 * PITCH) + ks * 32);
            if (ks < 3) {                    // prefetch next ks A frags
                #pragma unroll
                for (int fm = 0; fm < 4; fm++)
                    ldsm_x4(ah[nxt][fm], aA + fm * (16 * PITCH) + (ks + 1) * 32);
            }
            #pragma unroll
            for (int fm = 0; fm < 4; fm++)
                #pragma unroll
                for (int p = 0; p < 2; p++) {
                    mma16816(acc[fm][2 * p],     ah[cur][fm], bb[p][0], bb[p][2]);
                    mma16816(acc[fm][2 * p + 1], ah[cur][fm], bb[p][1], bb[p][3]);
                }
        }
    }

    // epilogue
    int gid = lid >> 2, tig = lid & 3;
    #pragma unroll
    for (int fm = 0; fm < 4; fm++) {
        int row0 = mBase + wm + fm * 16 + gid;
        #pragma unroll
        for (int fn = 0; fn < 4; fn++) {
            int col = nBase + wn + fn * 8 + tig * 2;
            float2 v0 = make_float2(acc[fm][fn][0], acc[fm][fn][1]);
            float2 v1 = make_float2(acc[fm][fn][2], acc[fm][fn][3]);
            if (sig) {
                v0.x = 1.f / (1.f + __expf(-v0.x));
                v0.y = 1.f / (1.f + __expf(-v0.y));
                v1.x = 1.f / (1.f + __expf(-v1.x));
                v1.y = 1.f / (1.f + __expf(-v1.y));
            }
            *(float2*)(C + (size_t)row0 * HD + col) = v0;
            *(float2*)(C + (size_t)(row0 + 8) * HD + col) = v1;
        }
    }
}

// ---------------------------------------------------------------------------
// WKV 3-phase segmented scan. Channel ch = b*HD + d. idx = seg*CH + ch.
// SEG=32 segments of 64 steps: 262144 threads => latency fully hidden.
// ---------------------------------------------------------------------------
__global__ void wkv_passA(const float* __restrict__ time_decay) {
    int idx = blockIdx.x * blockDim.x + threadIdx.x;   // 0..SEG*CH-1
    int d = idx % HD;
    int bc = idx / HD;
    int b = bc % BATCH;
    int seg = bc / BATCH;

    float td = -__expf(time_decay[d]);
    float num = 0.f, den = 0.f, mx = -1e38f;
    size_t base = (size_t)b * TLEN * HD + d;

    for (int t = seg * SEGLEN; t < (seg + 1) * SEGLEN; t++) {
        size_t off = base + (size_t)t * HD;
        float kt = g_k[off];
        float vt = g_v[off];
        float mfs = fmaxf(mx + td, kt);
        float e1s = __expf(mx + td - mfs);
        float e2s = __expf(kt - mfs);
        num = e1s * num + e2s * vt;
        den = e1s * den + e2s;
        mx  = mfs;
    }
    g_sn[idx] = num;
    g_sd[idx] = den;
    g_sm[idx] = mx;
}

__global__ void wkv_passB(const float* __restrict__ time_decay) {
    int ch = blockIdx.x * blockDim.x + threadIdx.x;   // 0..CH-1
    int d = ch % HD;
    float td = -__expf(time_decay[d]);
    float decL = td * (float)SEGLEN;

    float n0 = 0.f, d0 = 0.f, m0 = -1e38f;
    #pragma unroll
    for (int s = 0; s < SEG; s++) {
        int o = s * CH + ch;
        g_pn[o] = n0;
        g_pd[o] = d0;
        g_pm[o] = m0;
        float ns = g_sn[o], ds = g_sd[o], ms = g_sm[o];
        float mA = m0 + decL;
        float mn = fmaxf(ms, mA);
        float ea = __expf(mA - mn);
        float eb = __expf(ms - mn);
        n0 = ea * n0 + eb * ns;
        d0 = ea * d0 + eb * ds;
        m0 = mn;
    }
}

__global__ void wkv_passC(const float* __restrict__ time_decay,
                          const float* __restrict__ time_first) {
    int idx = blockIdx.x * blockDim.x + threadIdx.x;
    int d = idx % HD;
    int bc = idx / HD;
    int b = bc % BATCH;
    int seg = bc / BATCH;

    float td = -__expf(time_decay[d]);
    float tf = time_first[d];

    float num = g_pn[idx], den = g_pd[idx], mx = g_pm[idx];
    size_t base = (size_t)b * TLEN * HD + d;

    for (int t = seg * SEGLEN; t < (seg + 1) * SEGLEN; t++) {
        size_t off = base + (size_t)t * HD;
        float kt = g_k[off];
        float vt = g_v[off];
        float rt = g_r[off];

        float mfo = fmaxf(mx, kt + tf);
        float e1  = __expf(mx - mfo);
        float e2  = __expf(kt + tf - mfo);
        float out = (e1 * num + e2 * vt) / (e1 * den + e2);

        float mfs = fmaxf(mx + td, kt);
        float e1s = __expf(mx + td - mfs);
        float e2s = __expf(kt - mfs);
        num = e1s * num + e2s * vt;
        den = e1s * den + e2s;
        mx  = mfs;

        g_ak[off] = __float2half_rn(out * rt);
    }
}

// ---------------------------------------------------------------------------
// Launch
// ---------------------------------------------------------------------------
extern "C" void kernel_launch(void* const* d_in, const int* in_sizes, int n_in,
                              void* d_out, int out_size) {
    const float* hidden = (const float*)d_in[0];
    const float* time_decay = (const float*)d_in[1];
    const float* time_first = (const float*)d_in[2];
    const float* tmk = (const float*)d_in[3];
    const float* tmv = (const float*)d_in[4];
    const float* tmr = (const float*)d_in[5];
    const float* Wk = (const float*)d_in[6];
    const float* Wv = (const float*)d_in[7];
    const float* Wr = (const float*)d_in[8];
    const float* Wo = (const float*)d_in[9];

    __half *ak, *av, *ar, *wk, *wv, *wr, *wo;
    float *kb, *vb, *rb;
    cudaGetSymbolAddress((void**)&ak, g_ak);
    cudaGetSymbolAddress((void**)&av, g_av);
    cudaGetSymbolAddress((void**)&ar, g_ar);
    cudaGetSymbolAddress((void**)&wk, g_wk);
    cudaGetSymbolAddress((void**)&wv, g_wv);
    cudaGetSymbolAddress((void**)&wr, g_wr);
    cudaGetSymbolAddress((void**)&wo, g_wo);
    cudaGetSymbolAddress((void**)&kb, g_k);
    cudaGetSymbolAddress((void**)&vb, g_v);
    cudaGetSymbolAddress((void**)&rb, g_r);

    cudaFuncSetAttribute(gemm_f16, cudaFuncAttributeMaxDynamicSharedMemorySize, SMEM_GEMM);

    // 1. weight transposes (fused, z = matrix index)
    transpose_half4<<<dim3(HD / 32, HD / 32, 4), 256>>>(Wk, Wv, Wr, Wo,
                                                        wk, wv, wr, wo);

    // 2. mixes (fp16 planes)
    mix_kernel<<<(int)(TOT / 4 / 256), 256>>>(hidden, tmk, tmv, tmr);

    // 3. three input GEMMs in ONE launch (z selects k/v/r; z==2 gets sigmoid)
    dim3 grid3(HD / BN, MROWS / BM, 3);   // (16, 64, 3)
    gemm_f16<<<grid3, 256, SMEM_GEMM>>>(ak, av, ar, wk, wv, wr, kb, vb, rb, 2);

    // 4. WKV segmented scan (SEG=32), writes p into g_ak
    wkv_passA<<<SEG * CH / 256, 256>>>(time_decay);
    wkv_passB<<<CH / 256, 256>>>(time_decay);
    wkv_passC<<<SEG * CH / 256, 256>>>(time_decay, time_first);

    // 5. output GEMM
    dim3 grid1(HD / BN, MROWS / BM, 1);
    gemm_f16<<<grid1, 256, SMEM_GEMM>>>(ak, ak, ak, wo, wo, wo,
                                        (float*)d_out, (float*)d_out,
                                        (float*)d_out, -1);
}